// round 2
// baseline (speedup 1.0000x reference)
#include <cuda_runtime.h>
#include <cstdint>

// ---------------------------------------------------------------------------
// Neural CA, 16 steps. B=8, C=16, H=W=128, HID=128.
// Per step: sobel-x/y depthwise conv -> perception(48) -> w1(128x48)+relu ->
// w2(16x128) -> new = out + diff*mask(threefry) -> alive = maxpool3x3(alpha)>0.1
// -> out = new*alive.
// ---------------------------------------------------------------------------

#define BB 8
#define CC 16
#define HH 128
#define WW 128
#define HID 128
#define NSTEPS 16
#define NPIX (BB*HH*WW)          /* 131072 = 2^17 */
#define SELEM (BB*CC*HH*WW)      /* 2097152 */

__device__ float g_state[SELEM];
__device__ float g_new[SELEM];
__device__ unsigned char g_mask[NSTEPS*NPIX];
__device__ unsigned int g_keys[NSTEPS*2];

// ---------------------------------------------------------------------------
// threefry2x32 (exact JAX round structure)
// ---------------------------------------------------------------------------
__device__ __forceinline__ unsigned int rotl32(unsigned int v, int d) {
    return (v << d) | (v >> (32 - d));
}

__device__ __forceinline__ void threefry2x32(unsigned int k0, unsigned int k1,
                                             unsigned int x0, unsigned int x1,
                                             unsigned int& o0, unsigned int& o1) {
    unsigned int ks2 = k0 ^ k1 ^ 0x1BD11BDAu;
    x0 += k0; x1 += k1;
#define TF_G(r0,r1,r2,r3) \
    x0 += x1; x1 = rotl32(x1, r0); x1 ^= x0; \
    x0 += x1; x1 = rotl32(x1, r1); x1 ^= x0; \
    x0 += x1; x1 = rotl32(x1, r2); x1 ^= x0; \
    x0 += x1; x1 = rotl32(x1, r3); x1 ^= x0;
    TF_G(13,15,26,6);  x0 += k1;  x1 += ks2 + 1u;
    TF_G(17,29,16,24); x0 += ks2; x1 += k0  + 2u;
    TF_G(13,15,26,6);  x0 += k0;  x1 += k1  + 3u;
    TF_G(17,29,16,24); x0 += k1;  x1 += ks2 + 4u;
    TF_G(13,15,26,6);  x0 += ks2; x1 += k0  + 5u;
#undef TF_G
    o0 = x0; o1 = x1;
}

// Step keys: partitionable (foldlike) split of key(42) = (0, 42):
// key_s = threefry((0,42), (0, s))   (full output pair)
__global__ void k_keys() {
    int s = threadIdx.x;
    if (s < NSTEPS) {
        unsigned int o0, o1;
        threefry2x32(0u, 42u, 0u, (unsigned int)s, o0, o1);
        g_keys[2*s]   = o0;
        g_keys[2*s+1] = o1;
    }
}

// Masks: partitionable random_bits: bits_i = out0 ^ out1 of threefry(key_s,(0,i));
// uniform float = bitcast((bits>>9)|0x3f800000) - 1;  mask = (u < 0.5)
__global__ void k_mask() {
    int idx = blockIdx.x * blockDim.x + threadIdx.x;     // < NSTEPS*NPIX exactly
    int s = idx >> 17;
    unsigned int i = (unsigned int)(idx & (NPIX - 1));
    unsigned int o0, o1;
    threefry2x32(g_keys[2*s], g_keys[2*s+1], 0u, i, o0, o1);
    unsigned int bits = o0 ^ o1;
    float u = __uint_as_float((bits >> 9) | 0x3f800000u) - 1.0f;
    g_mask[idx] = (u < 0.5f) ? 1 : 0;
}

// ---------------------------------------------------------------------------
// Step A: perception + MLP + masked update.  Block = one (b, y) row, 128 thr.
// ---------------------------------------------------------------------------
__global__ __launch_bounds__(128, 4) void k_stepA(
    const float* __restrict__ src, float* __restrict__ dst,
    const float* __restrict__ w1, const float* __restrict__ b1,
    const float* __restrict__ w2, const float* __restrict__ b2,
    const unsigned char* __restrict__ msk)
{
    __shared__ float4 s_w1[HID * 12];   // [o][c/4], 24 KB
    __shared__ float4 s_w2[HID * 4];    // [o][k/4] (transposed), 8 KB
    __shared__ float  s_b1[HID];
    __shared__ float  s_b2[CC];

    int tid = threadIdx.x;
    {
        float* w1f = (float*)s_w1;
        for (int i = tid; i < HID * 48; i += 128) w1f[i] = w1[i];
        float* w2f = (float*)s_w2;
        for (int i = tid; i < HID * CC; i += 128) {
            int o = i >> 4, k = i & 15;
            w2f[i] = w2[k * HID + o];
        }
        if (tid < HID) s_b1[tid] = b1[tid];
        if (tid < CC)  s_b2[tid] = b2[tid];
    }
    __syncthreads();

    int b = blockIdx.x >> 7;
    int y = blockIdx.x & 127;
    int x = tid;
    bool ym = (y > 0), yp = (y < HH - 1), xm = (x > 0), xp = (x < WW - 1);

    // perception: [ident(16), sobel_x(16), sobel_y(16)]
    float P[48];
#pragma unroll
    for (int c = 0; c < CC; c++) {
        const float* pc = src + ((b * CC + c) * HH) * WW;
        const float* r0 = pc + (y - 1) * WW;
        const float* r1 = pc + y * WW;
        const float* r2 = pc + (y + 1) * WW;
        float v00 = (ym && xm) ? r0[x-1] : 0.0f;
        float v01 =  ym        ? r0[x]   : 0.0f;
        float v02 = (ym && xp) ? r0[x+1] : 0.0f;
        float v10 =  xm        ? r1[x-1] : 0.0f;
        float v11 =              r1[x];
        float v12 =  xp        ? r1[x+1] : 0.0f;
        float v20 = (yp && xm) ? r2[x-1] : 0.0f;
        float v21 =  yp        ? r2[x]   : 0.0f;
        float v22 = (yp && xp) ? r2[x+1] : 0.0f;
        P[c]      = v11;
        P[16 + c] = (v00 - v02 + 2.0f * (v10 - v12) + v20 - v22) * 0.125f;
        P[32 + c] = (v00 + 2.0f * v01 + v02 - v20 - 2.0f * v21 - v22) * 0.125f;
    }

    float diff[CC];
#pragma unroll
    for (int k = 0; k < CC; k++) diff[k] = s_b2[k];

#pragma unroll 2
    for (int o = 0; o < HID; o++) {
        const float4* wrow = s_w1 + o * 12;
        float4 w = wrow[0];
        float a0 = P[0] * w.x, a1 = P[1] * w.y, a2 = P[2] * w.z, a3 = P[3] * w.w;
#pragma unroll
        for (int j = 1; j < 12; j++) {
            w = wrow[j];
            a0 = fmaf(P[4*j+0], w.x, a0);
            a1 = fmaf(P[4*j+1], w.y, a1);
            a2 = fmaf(P[4*j+2], w.z, a2);
            a3 = fmaf(P[4*j+3], w.w, a3);
        }
        float h = ((a0 + a1) + (a2 + a3)) + s_b1[o];
        h = fmaxf(h, 0.0f);
        const float4* w2row = s_w2 + o * 4;
#pragma unroll
        for (int j = 0; j < 4; j++) {
            float4 q = w2row[j];
            diff[4*j+0] = fmaf(h, q.x, diff[4*j+0]);
            diff[4*j+1] = fmaf(h, q.y, diff[4*j+1]);
            diff[4*j+2] = fmaf(h, q.z, diff[4*j+2]);
            diff[4*j+3] = fmaf(h, q.w, diff[4*j+3]);
        }
    }

    float m = msk[(b * HH + y) * WW + x] ? 1.0f : 0.0f;
#pragma unroll
    for (int c = 0; c < CC; c++) {
        int idx = ((b * CC + c) * HH + y) * WW + x;
        dst[idx] = P[c] + diff[c] * m;
    }
}

// ---------------------------------------------------------------------------
// Step B: 3x3 max-pool of alpha (channel 3), alive gate, write next state.
// ---------------------------------------------------------------------------
__global__ __launch_bounds__(128) void k_stepB(const float* __restrict__ nw,
                                               float* __restrict__ dst)
{
    int b = blockIdx.x >> 7;
    int y = blockIdx.x & 127;
    int x = threadIdx.x;

    const float* alpha = nw + ((b * CC + 3) * HH) * WW;
    float m = -3.402823466e38f;
#pragma unroll
    for (int dy = -1; dy <= 1; dy++) {
        int yy = y + dy;
        if (yy < 0 || yy >= HH) continue;
        const float* row = alpha + yy * WW;
#pragma unroll
        for (int dx = -1; dx <= 1; dx++) {
            int xx = x + dx;
            if (xx < 0 || xx >= WW) continue;
            m = fmaxf(m, row[xx]);
        }
    }
    float alive = (m > 0.1f) ? 1.0f : 0.0f;
#pragma unroll
    for (int c = 0; c < CC; c++) {
        int idx = ((b * CC + c) * HH + y) * WW + x;
        dst[idx] = nw[idx] * alive;
    }
}

// ---------------------------------------------------------------------------
extern "C" void kernel_launch(void* const* d_in, const int* in_sizes, int n_in,
                              void* d_out, int out_size)
{
    (void)in_sizes; (void)n_in; (void)out_size;
    const float* x  = (const float*)d_in[0];
    const float* w1 = (const float*)d_in[1];
    const float* b1 = (const float*)d_in[2];
    const float* w2 = (const float*)d_in[3];
    const float* b2 = (const float*)d_in[4];
    float* out = (float*)d_out;

    float* pState = nullptr;
    float* pNew = nullptr;
    unsigned char* pMask = nullptr;
    cudaGetSymbolAddress((void**)&pState, g_state);
    cudaGetSymbolAddress((void**)&pNew,   g_new);
    cudaGetSymbolAddress((void**)&pMask,  g_mask);

    k_keys<<<1, NSTEPS>>>();
    k_mask<<<(NSTEPS * NPIX) / 256, 256>>>();

    for (int s = 0; s < NSTEPS; s++) {
        const float* src = (s == 0) ? x : pState;
        k_stepA<<<BB * HH, 128>>>(src, pNew, w1, b1, w2, b2, pMask + s * NPIX);
        float* dst = (s == NSTEPS - 1) ? out : pState;
        k_stepB<<<BB * HH, 128>>>(pNew, dst);
    }
}

// round 4
// speedup vs baseline: 1.0112x; 1.0112x over previous
#include <cuda_runtime.h>
#include <cuda_bf16.h>
#include <cstdint>

// ---------------------------------------------------------------------------
// Neural CA, 16 steps. B=8, C=16, H=W=128, HID=128.
// GEMM1 (48->128) via mma.sync bf16x2-split (target sm_103 has no tcgen05);
// GEMM2 (128->16) per-thread FFMA.
// ---------------------------------------------------------------------------

#define BB 8
#define CC 16
#define HH 128
#define WW 128
#define HID 128
#define NSTEPS 16
#define NPIX (BB*HH*WW)
#define SELEM (BB*CC*HH*WW)
#define KCH 48

#define A_STRIDE 56      /* bf16 elems, 112 B = 7 x 16B -> ldsm conflict-free */
#define B_STRIDE 136     /* bf16 elems, 272 B = 17 x 16B -> ldsm conflict-free */
#define H_STRIDE 68      /* fp32 elems, 272 B */

__device__ float g_state[SELEM];
__device__ float g_new[SELEM];
__device__ unsigned char g_mask[NSTEPS*NPIX];
__device__ unsigned int g_keys[NSTEPS*2];
// w1 transposed [k=48][n=128] padded to stride 136, bf16 hi/lo
__device__ __nv_bfloat16 g_w1Thi[KCH*B_STRIDE];
__device__ __nv_bfloat16 g_w1Tlo[KCH*B_STRIDE];

// ---------------------------------------------------------------------------
__device__ __forceinline__ uint32_t smem_u32(const void* p) {
    uint32_t a;
    asm("{ .reg .u64 t; cvta.to.shared.u64 t, %1; cvt.u32.u64 %0, t; }" : "=r"(a) : "l"(p));
    return a;
}
__device__ __forceinline__ void ldsm4(uint32_t* r, uint32_t addr) {
    asm volatile("ldmatrix.sync.aligned.m8n8.x4.shared.b16 {%0,%1,%2,%3}, [%4];"
        : "=r"(r[0]), "=r"(r[1]), "=r"(r[2]), "=r"(r[3]) : "r"(addr));
}
__device__ __forceinline__ void ldsm4t(uint32_t* r, uint32_t addr) {
    asm volatile("ldmatrix.sync.aligned.m8n8.x4.trans.shared.b16 {%0,%1,%2,%3}, [%4];"
        : "=r"(r[0]), "=r"(r[1]), "=r"(r[2]), "=r"(r[3]) : "r"(addr));
}
__device__ __forceinline__ void mma16816(float* c, const uint32_t* a, const uint32_t* b) {
    asm volatile("mma.sync.aligned.m16n8k16.row.col.f32.bf16.bf16.f32 "
        "{%0,%1,%2,%3}, {%4,%5,%6,%7}, {%8,%9}, {%0,%1,%2,%3};"
        : "+f"(c[0]), "+f"(c[1]), "+f"(c[2]), "+f"(c[3])
        : "r"(a[0]), "r"(a[1]), "r"(a[2]), "r"(a[3]), "r"(b[0]), "r"(b[1]));
}

// ---------------------------------------------------------------------------
// threefry2x32 (exact JAX round structure, partitionable path)
// ---------------------------------------------------------------------------
__device__ __forceinline__ unsigned int rotl32(unsigned int v, int d) {
    return (v << d) | (v >> (32 - d));
}
__device__ __forceinline__ void threefry2x32(unsigned int k0, unsigned int k1,
                                             unsigned int x0, unsigned int x1,
                                             unsigned int& o0, unsigned int& o1) {
    unsigned int ks2 = k0 ^ k1 ^ 0x1BD11BDAu;
    x0 += k0; x1 += k1;
#define TF_G(r0,r1,r2,r3) \
    x0 += x1; x1 = rotl32(x1, r0); x1 ^= x0; \
    x0 += x1; x1 = rotl32(x1, r1); x1 ^= x0; \
    x0 += x1; x1 = rotl32(x1, r2); x1 ^= x0; \
    x0 += x1; x1 = rotl32(x1, r3); x1 ^= x0;
    TF_G(13,15,26,6);  x0 += k1;  x1 += ks2 + 1u;
    TF_G(17,29,16,24); x0 += ks2; x1 += k0  + 2u;
    TF_G(13,15,26,6);  x0 += k0;  x1 += k1  + 3u;
    TF_G(17,29,16,24); x0 += k1;  x1 += ks2 + 4u;
    TF_G(13,15,26,6);  x0 += ks2; x1 += k0  + 5u;
#undef TF_G
    o0 = x0; o1 = x1;
}

__global__ void k_keys() {
    int s = threadIdx.x;
    if (s < NSTEPS) {
        unsigned int o0, o1;
        threefry2x32(0u, 42u, 0u, (unsigned int)s, o0, o1);
        g_keys[2*s] = o0; g_keys[2*s+1] = o1;
    }
}

__global__ void k_mask() {
    int idx = blockIdx.x * blockDim.x + threadIdx.x;
    int s = idx >> 17;
    unsigned int i = (unsigned int)(idx & (NPIX - 1));
    unsigned int o0, o1;
    threefry2x32(g_keys[2*s], g_keys[2*s+1], 0u, i, o0, o1);
    unsigned int bits = o0 ^ o1;
    float u = __uint_as_float((bits >> 9) | 0x3f800000u) - 1.0f;
    g_mask[idx] = (u < 0.5f) ? 1 : 0;
}

// Pre-split w1 into bf16 hi/lo, transposed [c][o] with padded stride.
__global__ void k_wsplit(const float* __restrict__ w1) {
    int i = blockIdx.x * blockDim.x + threadIdx.x;   // 6144 = 128*48
    if (i >= HID * KCH) return;
    int o = i / KCH, c = i % KCH;
    float v = w1[i];
    __nv_bfloat16 hi = __float2bfloat16(v);
    float lo = v - __bfloat162float(hi);
    g_w1Thi[c * B_STRIDE + o] = hi;
    g_w1Tlo[c * B_STRIDE + o] = __float2bfloat16(lo);
}

// ---------------------------------------------------------------------------
// Step A. Block = one (b, y) row of 128 pixels, 128 threads (4 warps).
// ---------------------------------------------------------------------------
#define OFF_AH 0                         /* 128*56*2 = 14336 */
#define OFF_AL 14336
#define OFF_BH 28672                     /* 48*136*2 = 13056 */
#define OFF_BL 41728
#define OFF_H  54784                     /* 128*68*4 = 34816 */
#define OFF_W2 89600                     /* 8192 */
#define OFF_B1 97792                     /* 512 */
#define OFF_B2 98304                     /* 64 */
#define SMEM_TOT 98368

__global__ __launch_bounds__(128)
void k_stepA(const float* __restrict__ src, float* __restrict__ dst,
             const float* __restrict__ b1, const float* __restrict__ w2,
             const float* __restrict__ b2, const unsigned char* __restrict__ msk)
{
    extern __shared__ char smem[];
    uint32_t sb = smem_u32(smem);

    int tid = threadIdx.x;
    int l   = tid & 31;
    int wid = tid >> 5;
    int wbase = wid * 32;

    // --- stage w1T hi/lo tiles, w2 (transposed), biases ---
    {
        const uint4* sBH = (const uint4*)g_w1Thi;
        const uint4* sBL = (const uint4*)g_w1Tlo;
        uint4* dBH = (uint4*)(smem + OFF_BH);
        uint4* dBL = (uint4*)(smem + OFF_BL);
        for (int i = tid; i < (KCH * B_STRIDE * 2) / 16; i += 128) {
            dBH[i] = sBH[i]; dBL[i] = sBL[i];
        }
        float* w2f = (float*)(smem + OFF_W2);
        for (int i = tid; i < HID * CC; i += 128) {
            int o = i >> 4, k = i & 15;
            w2f[i] = w2[k * HID + o];      // transposed: [o][k]
        }
        float* bs1 = (float*)(smem + OFF_B1);
        float* bs2 = (float*)(smem + OFF_B2);
        if (tid < HID) bs1[tid] = b1[tid];
        if (tid < CC)  bs2[tid] = b2[tid];
    }
    __syncthreads();

    // --- perception + split -> A tiles (row = pixel, col = channel) ---
    int b = blockIdx.x >> 7;
    int y = blockIdx.x & 127;
    int x = tid;
    bool ym = (y > 0), yp = (y < HH - 1), xm = (x > 0), xp = (x < WW - 1);

    __nv_bfloat16* aH = (__nv_bfloat16*)(smem + OFF_AH) + tid * A_STRIDE;
    __nv_bfloat16* aL = (__nv_bfloat16*)(smem + OFF_AL) + tid * A_STRIDE;

#pragma unroll
    for (int c = 0; c < CC; c++) {
        const float* pc = src + ((b * CC + c) * HH) * WW;
        const float* r0 = pc + (y - 1) * WW;
        const float* r1 = pc + y * WW;
        const float* r2 = pc + (y + 1) * WW;
        float v00 = (ym && xm) ? r0[x-1] : 0.0f;
        float v01 =  ym        ? r0[x]   : 0.0f;
        float v02 = (ym && xp) ? r0[x+1] : 0.0f;
        float v10 =  xm        ? r1[x-1] : 0.0f;
        float v11 =              r1[x];
        float v12 =  xp        ? r1[x+1] : 0.0f;
        float v20 = (yp && xm) ? r2[x-1] : 0.0f;
        float v21 =  yp        ? r2[x]   : 0.0f;
        float v22 = (yp && xp) ? r2[x+1] : 0.0f;
        float sx = (v00 - v02 + 2.0f * (v10 - v12) + v20 - v22) * 0.125f;
        float sy = (v00 + 2.0f * v01 + v02 - v20 - 2.0f * v21 - v22) * 0.125f;

        __nv_bfloat16 h0 = __float2bfloat16(v11);
        __nv_bfloat16 h1 = __float2bfloat16(sx);
        __nv_bfloat16 h2 = __float2bfloat16(sy);
        aH[c]      = h0;  aL[c]      = __float2bfloat16(v11 - __bfloat162float(h0));
        aH[16 + c] = h1;  aL[16 + c] = __float2bfloat16(sx  - __bfloat162float(h1));
        aH[32 + c] = h2;  aL[32 + c] = __float2bfloat16(sy  - __bfloat162float(h2));
    }
    __syncwarp();

    // --- load A fragments (per warp: rows wbase..wbase+31) ---
    uint32_t ah[2][3][4], al[2][3][4];
    {
        uint32_t rowb = sb + OFF_AH;
        uint32_t rowl = sb + OFF_AL;
        uint32_t roff = (uint32_t)(wbase + (l & 15)) * (A_STRIDE * 2) + (uint32_t)(l >> 4) * 16;
#pragma unroll
        for (int m = 0; m < 2; m++) {
#pragma unroll
            for (int k = 0; k < 3; k++) {
                uint32_t off = roff + m * 16 * (A_STRIDE * 2) + k * 32;
                ldsm4(ah[m][k], rowb + off);
                ldsm4(al[m][k], rowl + off);
            }
        }
    }

    const float* bs1 = (const float*)(smem + OFF_B1);
    const float* bs2 = (const float*)(smem + OFF_B2);
    const float4* w2t = (const float4*)(smem + OFF_W2);
    float* sH = (float*)(smem + OFF_H);

    float diff[CC];
#pragma unroll
    for (int k = 0; k < CC; k++) diff[k] = bs2[k];

    int gid = l >> 2, tig = l & 3;

#pragma unroll
    for (int pass = 0; pass < 2; pass++) {
        float acc[8][2][4];
#pragma unroll
        for (int nt = 0; nt < 8; nt++)
#pragma unroll
            for (int m = 0; m < 2; m++)
#pragma unroll
                for (int q = 0; q < 4; q++) acc[nt][m][q] = 0.0f;

        // GEMM1: acc += Ahi*Bhi + Ahi*Blo + Alo*Bhi
        uint32_t bro = (uint32_t)(l & 15) * (B_STRIDE * 2) + (uint32_t)(l >> 4) * 16;
#pragma unroll
        for (int jj = 0; jj < 4; jj++) {
            uint32_t ncol = (uint32_t)(pass * 64 + jj * 16) * 2;
#pragma unroll
            for (int k = 0; k < 3; k++) {
                uint32_t off = (uint32_t)k * 16 * (B_STRIDE * 2) + bro + ncol;
                uint32_t bh[4], bl[4];
                ldsm4t(bh, sb + OFF_BH + off);
                ldsm4t(bl, sb + OFF_BL + off);
#pragma unroll
                for (int m = 0; m < 2; m++) {
                    mma16816(acc[jj*2+0][m], ah[m][k], bh + 0);
                    mma16816(acc[jj*2+1][m], ah[m][k], bh + 2);
                    mma16816(acc[jj*2+0][m], ah[m][k], bl + 0);
                    mma16816(acc[jj*2+1][m], ah[m][k], bl + 2);
                    mma16816(acc[jj*2+0][m], al[m][k], bh + 0);
                    mma16816(acc[jj*2+1][m], al[m][k], bh + 2);
                }
            }
        }

        // epilogue: h = relu(acc + b1) -> smem [pixel][H_STRIDE]
#pragma unroll
        for (int m = 0; m < 2; m++) {
#pragma unroll
            for (int nt = 0; nt < 8; nt++) {
                const float* c = acc[nt][m];
                int p1 = wbase + m * 16 + gid;
                int o1 = nt * 8 + tig * 2;
                float bb0 = bs1[pass * 64 + o1];
                float bb1 = bs1[pass * 64 + o1 + 1];
                float2 v0 = make_float2(fmaxf(c[0] + bb0, 0.0f), fmaxf(c[1] + bb1, 0.0f));
                float2 v1 = make_float2(fmaxf(c[2] + bb0, 0.0f), fmaxf(c[3] + bb1, 0.0f));
                *(float2*)(sH + p1 * H_STRIDE + o1) = v0;
                *(float2*)(sH + (p1 + 8) * H_STRIDE + o1) = v1;
            }
        }
        __syncwarp();

        // GEMM2 partial: thread = its own pixel (same warp wrote these rows)
        const float* hrow = sH + tid * H_STRIDE;
#pragma unroll
        for (int i = 0; i < 16; i++) {
            float4 hv = *(const float4*)(hrow + i * 4);
            int ob = pass * 64 + i * 4;
#pragma unroll
            for (int q = 0; q < 4; q++) {
                float h = (q == 0) ? hv.x : (q == 1) ? hv.y : (q == 2) ? hv.z : hv.w;
                const float4* w2row = w2t + (ob + q) * 4;
#pragma unroll
                for (int r = 0; r < 4; r++) {
                    float4 w = w2row[r];
                    diff[4*r+0] = fmaf(h, w.x, diff[4*r+0]);
                    diff[4*r+1] = fmaf(h, w.y, diff[4*r+1]);
                    diff[4*r+2] = fmaf(h, w.z, diff[4*r+2]);
                    diff[4*r+3] = fmaf(h, w.w, diff[4*r+3]);
                }
            }
        }
        __syncwarp();   // before next pass overwrites sH
    }

    // --- masked update (reload ident from src; L1-hot) ---
    float m = msk[(b * HH + y) * WW + x] ? 1.0f : 0.0f;
#pragma unroll
    for (int c = 0; c < CC; c++) {
        int idx = ((b * CC + c) * HH + y) * WW + x;
        dst[idx] = src[idx] + diff[c] * m;
    }
}

// ---------------------------------------------------------------------------
// Step B: 3x3 max-pool of alpha (channel 3), alive gate.
// ---------------------------------------------------------------------------
__global__ __launch_bounds__(128) void k_stepB(const float* __restrict__ nw,
                                               float* __restrict__ dst)
{
    int b = blockIdx.x >> 7;
    int y = blockIdx.x & 127;
    int x = threadIdx.x;

    const float* alpha = nw + ((b * CC + 3) * HH) * WW;
    float m = -3.402823466e38f;
#pragma unroll
    for (int dy = -1; dy <= 1; dy++) {
        int yy = y + dy;
        if (yy < 0 || yy >= HH) continue;
        const float* row = alpha + yy * WW;
#pragma unroll
        for (int dx = -1; dx <= 1; dx++) {
            int xx = x + dx;
            if (xx < 0 || xx >= WW) continue;
            m = fmaxf(m, row[xx]);
        }
    }
    float alive = (m > 0.1f) ? 1.0f : 0.0f;
#pragma unroll
    for (int c = 0; c < CC; c++) {
        int idx = ((b * CC + c) * HH + y) * WW + x;
        dst[idx] = nw[idx] * alive;
    }
}

// ---------------------------------------------------------------------------
extern "C" void kernel_launch(void* const* d_in, const int* in_sizes, int n_in,
                              void* d_out, int out_size)
{
    (void)in_sizes; (void)n_in; (void)out_size;
    const float* x  = (const float*)d_in[0];
    const float* w1 = (const float*)d_in[1];
    const float* b1 = (const float*)d_in[2];
    const float* w2 = (const float*)d_in[3];
    const float* b2 = (const float*)d_in[4];
    float* out = (float*)d_out;

    float* pState = nullptr;
    float* pNew = nullptr;
    unsigned char* pMask = nullptr;
    cudaGetSymbolAddress((void**)&pState, g_state);
    cudaGetSymbolAddress((void**)&pNew,   g_new);
    cudaGetSymbolAddress((void**)&pMask,  g_mask);

    cudaFuncSetAttribute(k_stepA, cudaFuncAttributeMaxDynamicSharedMemorySize, SMEM_TOT);

    k_keys<<<1, NSTEPS>>>();
    k_mask<<<(NSTEPS * NPIX) / 256, 256>>>();
    k_wsplit<<<(HID * KCH + 127) / 128, 128>>>(w1);

    for (int s = 0; s < NSTEPS; s++) {
        const float* src = (s == 0) ? x : pState;
        k_stepA<<<BB * HH, 128, SMEM_TOT>>>(src, pNew, b1, w2, b2, pMask + s * NPIX);
        float* dst = (s == NSTEPS - 1) ? out : pState;
        k_stepB<<<BB * HH, 128>>>(pNew, dst);
    }
}

// round 9
// speedup vs baseline: 1.7261x; 1.7069x over previous
#include <cuda_runtime.h>
#include <cuda_bf16.h>
#include <cstdint>

// ---------------------------------------------------------------------------
// Neural CA, 16 steps. B=8, C=16, H=W=128, HID=128.
// GEMM1 (48->128) + GEMM2 (128->16) both on mma.sync bf16 hi/lo split,
// h passed register-to-register via fragment-layout reuse (FA2 trick).
// ---------------------------------------------------------------------------

#define BB 8
#define CC 16
#define HH 128
#define WW 128
#define HID 128
#define NSTEPS 16
#define NPIX (BB*HH*WW)
#define SELEM (BB*CC*HH*WW)
#define KCH 48
#define NTILES (BB*HH)           /* 1024 row-tiles */
#define GRID_A 444               /* 148 SMs x 3 blocks */

#define A_STRIDE 56      /* bf16: 112B = 7x16B, ldsm conflict-free */
#define B_STRIDE 136     /* bf16: 272B = 17x16B, ldsm conflict-free */
#define W2_STRIDE 24     /* bf16: 48B = 3x16B, ldsm conflict-free */

__device__ float g_state[SELEM];
__device__ float g_new[SELEM];
__device__ unsigned char g_mask[NSTEPS*NPIX];
__device__ unsigned int g_keys[NSTEPS*2];
__device__ __nv_bfloat16 g_w1Thi[KCH*B_STRIDE];    // [c=48][o=128] padded
__device__ __nv_bfloat16 g_w1Tlo[KCH*B_STRIDE];
__device__ __nv_bfloat16 g_w2Thi[HID*W2_STRIDE];   // [k=128][n=16] padded
__device__ __nv_bfloat16 g_w2Tlo[HID*W2_STRIDE];

// ---------------------------------------------------------------------------
__device__ __forceinline__ uint32_t smem_u32(const void* p) {
    uint32_t a;
    asm("{ .reg .u64 t; cvta.to.shared.u64 t, %1; cvt.u32.u64 %0, t; }" : "=r"(a) : "l"(p));
    return a;
}
__device__ __forceinline__ void ldsm4(uint32_t* r, uint32_t addr) {
    asm volatile("ldmatrix.sync.aligned.m8n8.x4.shared.b16 {%0,%1,%2,%3}, [%4];"
        : "=r"(r[0]), "=r"(r[1]), "=r"(r[2]), "=r"(r[3]) : "r"(addr));
}
__device__ __forceinline__ void ldsm4t(uint32_t* r, uint32_t addr) {
    asm volatile("ldmatrix.sync.aligned.m8n8.x4.trans.shared.b16 {%0,%1,%2,%3}, [%4];"
        : "=r"(r[0]), "=r"(r[1]), "=r"(r[2]), "=r"(r[3]) : "r"(addr));
}
__device__ __forceinline__ void mma16816(float* c, const uint32_t* a, const uint32_t* b) {
    asm volatile("mma.sync.aligned.m16n8k16.row.col.f32.bf16.bf16.f32 "
        "{%0,%1,%2,%3}, {%4,%5,%6,%7}, {%8,%9}, {%0,%1,%2,%3};"
        : "+f"(c[0]), "+f"(c[1]), "+f"(c[2]), "+f"(c[3])
        : "r"(a[0]), "r"(a[1]), "r"(a[2]), "r"(a[3]), "r"(b[0]), "r"(b[1]));
}
__device__ __forceinline__ uint32_t pack_bf16x2(float a, float b) {
    __nv_bfloat162 v;
    v.x = __float2bfloat16(a);
    v.y = __float2bfloat16(b);
    return *(uint32_t*)&v;
}

// ---------------------------------------------------------------------------
// threefry2x32 (exact JAX round structure, partitionable path)
// ---------------------------------------------------------------------------
__device__ __forceinline__ unsigned int rotl32(unsigned int v, int d) {
    return (v << d) | (v >> (32 - d));
}
__device__ __forceinline__ void threefry2x32(unsigned int k0, unsigned int k1,
                                             unsigned int x0, unsigned int x1,
                                             unsigned int& o0, unsigned int& o1) {
    unsigned int ks2 = k0 ^ k1 ^ 0x1BD11BDAu;
    x0 += k0; x1 += k1;
#define TF_G(r0,r1,r2,r3) \
    x0 += x1; x1 = rotl32(x1, r0); x1 ^= x0; \
    x0 += x1; x1 = rotl32(x1, r1); x1 ^= x0; \
    x0 += x1; x1 = rotl32(x1, r2); x1 ^= x0; \
    x0 += x1; x1 = rotl32(x1, r3); x1 ^= x0;
    TF_G(13,15,26,6);  x0 += k1;  x1 += ks2 + 1u;
    TF_G(17,29,16,24); x0 += ks2; x1 += k0  + 2u;
    TF_G(13,15,26,6);  x0 += k0;  x1 += k1  + 3u;
    TF_G(17,29,16,24); x0 += k1;  x1 += ks2 + 4u;
    TF_G(13,15,26,6);  x0 += ks2; x1 += k0  + 5u;
#undef TF_G
    o0 = x0; o1 = x1;
}

__global__ void k_keys() {
    int s = threadIdx.x;
    if (s < NSTEPS) {
        unsigned int o0, o1;
        threefry2x32(0u, 42u, 0u, (unsigned int)s, o0, o1);
        g_keys[2*s] = o0; g_keys[2*s+1] = o1;
    }
}

__global__ void k_mask() {
    int idx = blockIdx.x * blockDim.x + threadIdx.x;
    int s = idx >> 17;
    unsigned int i = (unsigned int)(idx & (NPIX - 1));
    unsigned int o0, o1;
    threefry2x32(g_keys[2*s], g_keys[2*s+1], 0u, i, o0, o1);
    unsigned int bits = o0 ^ o1;
    float u = __uint_as_float((bits >> 9) | 0x3f800000u) - 1.0f;
    g_mask[idx] = (u < 0.5f) ? 1 : 0;
}

// Pre-split w1 (transposed [c][o]) and w2 (transposed [k][n]) to bf16 hi/lo.
__global__ void k_wsplit(const float* __restrict__ w1, const float* __restrict__ w2) {
    int i = blockIdx.x * blockDim.x + threadIdx.x;
    if (i < HID * KCH) {                       // w1[o=128][c=48]
        int o = i / KCH, c = i % KCH;
        float v = w1[i];
        __nv_bfloat16 hi = __float2bfloat16(v);
        g_w1Thi[c * B_STRIDE + o] = hi;
        g_w1Tlo[c * B_STRIDE + o] = __float2bfloat16(v - __bfloat162float(hi));
    } else if (i < HID * KCH + CC * HID) {     // w2[n=16][k=128]
        int j = i - HID * KCH;
        int n = j >> 7, k = j & 127;
        float v = w2[n * HID + k];
        __nv_bfloat16 hi = __float2bfloat16(v);
        g_w2Thi[k * W2_STRIDE + n] = hi;
        g_w2Tlo[k * W2_STRIDE + n] = __float2bfloat16(v - __bfloat162float(hi));
    }
}

// ---------------------------------------------------------------------------
// Step A. Grid-stride over 1024 row-tiles; block = 128 thr (4 warps).
// ---------------------------------------------------------------------------
#define OFF_AH  0                        /* 128*56*2 = 14336 */
#define OFF_AL  14336
#define OFF_BH  28672                    /* 48*136*2 = 13056 */
#define OFF_BL  41728
#define OFF_W2H 54784                    /* 128*24*2 = 6144 */
#define OFF_W2L 60928
#define OFF_B1  67072                    /* 512 */
#define OFF_B2  67584                    /* 64 */
#define SMEM_TOT 67648

__global__ __launch_bounds__(128, 3)
void k_stepA(const float* __restrict__ src, float* __restrict__ dst,
             const float* __restrict__ b1, const float* __restrict__ b2,
             const unsigned char* __restrict__ msk)
{
    extern __shared__ char smem[];
    uint32_t sb = smem_u32(smem);

    int tid = threadIdx.x;
    int l   = tid & 31;
    int wid = tid >> 5;
    int wbase = wid * 32;
    int gid = l >> 2, tig = l & 3;

    // --- stage weights once per block ---
    {
        const uint4* s1h = (const uint4*)g_w1Thi;
        const uint4* s1l = (const uint4*)g_w1Tlo;
        uint4* d1h = (uint4*)(smem + OFF_BH);
        uint4* d1l = (uint4*)(smem + OFF_BL);
        for (int i = tid; i < (KCH * B_STRIDE * 2) / 16; i += 128) {
            d1h[i] = s1h[i]; d1l[i] = s1l[i];
        }
        const uint4* s2h = (const uint4*)g_w2Thi;
        const uint4* s2l = (const uint4*)g_w2Tlo;
        uint4* d2h = (uint4*)(smem + OFF_W2H);
        uint4* d2l = (uint4*)(smem + OFF_W2L);
        for (int i = tid; i < (HID * W2_STRIDE * 2) / 16; i += 128) {
            d2h[i] = s2h[i]; d2l[i] = s2l[i];
        }
        float* bs1 = (float*)(smem + OFF_B1);
        float* bs2 = (float*)(smem + OFF_B2);
        if (tid < HID) bs1[tid] = b1[tid];
        if (tid < CC)  bs2[tid] = b2[tid];
    }
    __syncthreads();

    const float* bs1 = (const float*)(smem + OFF_B1);
    const float* bs2 = (const float*)(smem + OFF_B2);

    for (int tile = blockIdx.x; tile < NTILES; tile += GRID_A) {
        int b = tile >> 7;
        int y = tile & 127;
        int x = tid;
        bool ym = (y > 0), yp = (y < HH - 1), xm = (x > 0), xp = (x < WW - 1);

        // --- perception + hi/lo split -> warp-local A tiles ---
        __nv_bfloat16* aH = (__nv_bfloat16*)(smem + OFF_AH) + tid * A_STRIDE;
        __nv_bfloat16* aL = (__nv_bfloat16*)(smem + OFF_AL) + tid * A_STRIDE;
#pragma unroll
        for (int c = 0; c < CC; c++) {
            const float* pc = src + ((b * CC + c) * HH) * WW;
            const float* r0 = pc + (y - 1) * WW;
            const float* r1 = pc + y * WW;
            const float* r2 = pc + (y + 1) * WW;
            float v00 = (ym && xm) ? r0[x-1] : 0.0f;
            float v01 =  ym        ? r0[x]   : 0.0f;
            float v02 = (ym && xp) ? r0[x+1] : 0.0f;
            float v10 =  xm        ? r1[x-1] : 0.0f;
            float v11 =              r1[x];
            float v12 =  xp        ? r1[x+1] : 0.0f;
            float v20 = (yp && xm) ? r2[x-1] : 0.0f;
            float v21 =  yp        ? r2[x]   : 0.0f;
            float v22 = (yp && xp) ? r2[x+1] : 0.0f;
            float sx = (v00 - v02 + 2.0f * (v10 - v12) + v20 - v22) * 0.125f;
            float sy = (v00 + 2.0f * v01 + v02 - v20 - 2.0f * v21 - v22) * 0.125f;
            __nv_bfloat16 h0 = __float2bfloat16(v11);
            __nv_bfloat16 h1 = __float2bfloat16(sx);
            __nv_bfloat16 h2 = __float2bfloat16(sy);
            aH[c]      = h0;  aL[c]      = __float2bfloat16(v11 - __bfloat162float(h0));
            aH[16 + c] = h1;  aL[16 + c] = __float2bfloat16(sx  - __bfloat162float(h1));
            aH[32 + c] = h2;  aL[32 + c] = __float2bfloat16(sy  - __bfloat162float(h2));
        }
        __syncwarp();

        // --- A fragments (warp-local rows) ---
        uint32_t ah[2][3][4], al[2][3][4];
        {
            uint32_t roff = (uint32_t)(wbase + (l & 15)) * (A_STRIDE * 2) + (uint32_t)(l >> 4) * 16;
#pragma unroll
            for (int m = 0; m < 2; m++)
#pragma unroll
                for (int k = 0; k < 3; k++) {
                    uint32_t off = roff + m * 16 * (A_STRIDE * 2) + k * 32;
                    ldsm4(ah[m][k], sb + OFF_AH + off);
                    ldsm4(al[m][k], sb + OFF_AL + off);
                }
        }

        // diff accumulators (GEMM2 C-frags), init with b2
        float d2[2][2][4];
#pragma unroll
        for (int m = 0; m < 2; m++)
#pragma unroll
            for (int n = 0; n < 2; n++) {
                float q0 = bs2[n * 8 + tig * 2];
                float q1 = bs2[n * 8 + tig * 2 + 1];
                d2[m][n][0] = q0; d2[m][n][1] = q1;
                d2[m][n][2] = q0; d2[m][n][3] = q1;
            }

#pragma unroll
        for (int pass = 0; pass < 2; pass++) {
            float acc[8][2][4];
#pragma unroll
            for (int nt = 0; nt < 8; nt++)
#pragma unroll
                for (int m = 0; m < 2; m++)
#pragma unroll
                    for (int q = 0; q < 4; q++) acc[nt][m][q] = 0.0f;

            // GEMM1: acc += Ahi*Bhi + Ahi*Blo + Alo*Bhi
            uint32_t bro = (uint32_t)(l & 15) * (B_STRIDE * 2) + (uint32_t)(l >> 4) * 16;
#pragma unroll
            for (int jj = 0; jj < 4; jj++) {
                uint32_t ncol = (uint32_t)(pass * 64 + jj * 16) * 2;
#pragma unroll
                for (int k = 0; k < 3; k++) {
                    uint32_t off = (uint32_t)k * 16 * (B_STRIDE * 2) + bro + ncol;
                    uint32_t bh[4], bl[4];
                    ldsm4t(bh, sb + OFF_BH + off);
                    ldsm4t(bl, sb + OFF_BL + off);
#pragma unroll
                    for (int m = 0; m < 2; m++) {
                        mma16816(acc[jj*2+0][m], ah[m][k], bh + 0);
                        mma16816(acc[jj*2+1][m], ah[m][k], bh + 2);
                        mma16816(acc[jj*2+0][m], ah[m][k], bl + 0);
                        mma16816(acc[jj*2+1][m], ah[m][k], bl + 2);
                        mma16816(acc[jj*2+0][m], al[m][k], bh + 0);
                        mma16816(acc[jj*2+1][m], al[m][k], bh + 2);
                    }
                }
            }

            // GEMM2 partial: h = relu(acc+b1) split hi/lo in regs -> mma
#pragma unroll
            for (int kk = 0; kk < 4; kk++) {
                uint32_t woff = ((uint32_t)(pass * 64 + kk * 16 + (l & 15)) * W2_STRIDE
                                 + (uint32_t)(l >> 4) * 8) * 2;
                uint32_t wh[4], wl[4];
                ldsm4t(wh, sb + OFF_W2H + woff);
                ldsm4t(wl, sb + OFF_W2L + woff);
#pragma unroll
                for (int m = 0; m < 2; m++) {
                    const float* c0 = acc[2*kk][m];
                    const float* c1 = acc[2*kk+1][m];
                    float b00 = bs1[pass*64 + (2*kk)*8 + tig*2];
                    float b01 = bs1[pass*64 + (2*kk)*8 + tig*2 + 1];
                    float b10 = bs1[pass*64 + (2*kk+1)*8 + tig*2];
                    float b11 = bs1[pass*64 + (2*kk+1)*8 + tig*2 + 1];
                    float h0 = fmaxf(c0[0] + b00, 0.0f), h1 = fmaxf(c0[1] + b01, 0.0f);
                    float h2 = fmaxf(c0[2] + b00, 0.0f), h3 = fmaxf(c0[3] + b01, 0.0f);
                    float h4 = fmaxf(c1[0] + b10, 0.0f), h5 = fmaxf(c1[1] + b11, 0.0f);
                    float h6 = fmaxf(c1[2] + b10, 0.0f), h7 = fmaxf(c1[3] + b11, 0.0f);
                    uint32_t ahi[4], alo[4];
                    ahi[0] = pack_bf16x2(h0, h1);
                    ahi[1] = pack_bf16x2(h2, h3);
                    ahi[2] = pack_bf16x2(h4, h5);
                    ahi[3] = pack_bf16x2(h6, h7);
                    {
                        __nv_bfloat162* hp = (__nv_bfloat162*)ahi;
                        alo[0] = pack_bf16x2(h0 - __bfloat162float(hp[0].x), h1 - __bfloat162float(hp[0].y));
                        alo[1] = pack_bf16x2(h2 - __bfloat162float(hp[1].x), h3 - __bfloat162float(hp[1].y));
                        alo[2] = pack_bf16x2(h4 - __bfloat162float(hp[2].x), h5 - __bfloat162float(hp[2].y));
                        alo[3] = pack_bf16x2(h6 - __bfloat162float(hp[3].x), h7 - __bfloat162float(hp[3].y));
                    }
                    mma16816(d2[m][0], ahi, wh + 0);
                    mma16816(d2[m][1], ahi, wh + 2);
                    mma16816(d2[m][0], ahi, wl + 0);
                    mma16816(d2[m][1], ahi, wl + 2);
                    mma16816(d2[m][0], alo, wh + 0);
                    mma16816(d2[m][1], alo, wh + 2);
                }
            }
        }

        // --- masked update straight from fragments ---
        const unsigned char* mrow = msk + (b * HH + y) * WW;
#pragma unroll
        for (int m = 0; m < 2; m++) {
            int px0 = wbase + m * 16 + gid;
            int px1 = px0 + 8;
            float m0 = mrow[px0] ? 1.0f : 0.0f;
            float m1 = mrow[px1] ? 1.0f : 0.0f;
#pragma unroll
            for (int n = 0; n < 2; n++) {
                int c0 = n * 8 + tig * 2;
                const float* d = d2[m][n];
                int i00 = ((b * CC + c0) * HH + y) * WW + px0;
                int i10 = ((b * CC + c0 + 1) * HH + y) * WW + px0;
                dst[i00]     = src[i00]     + d[0] * m0;
                dst[i10]     = src[i10]     + d[1] * m0;
                dst[i00 + 8] = src[i00 + 8] + d[2] * m1;
                dst[i10 + 8] = src[i10 + 8] + d[3] * m1;
            }
        }
        __syncwarp();   // A smem reused next tile (warp-local)
    }
}

// ---------------------------------------------------------------------------
// Step B: 3x3 max-pool of alpha, alive gate. 4 pixels/thread via float4.
// ---------------------------------------------------------------------------
__global__ __launch_bounds__(256) void k_stepB(const float* __restrict__ nw,
                                               float* __restrict__ dst)
{
    int g = blockIdx.x * 256 + threadIdx.x;     // pixel-group id
    int p4 = g * 4;
    int b = p4 >> 14;
    int rem = p4 & 16383;
    int y = rem >> 7;
    int x0 = rem & 127;                          // multiple of 4

    const float* alpha = nw + ((b * CC + 3) * HH) * WW;
    const float NEG = -3.402823466e38f;
    float h[4]; h[0] = h[1] = h[2] = h[3] = NEG;
#pragma unroll
    for (int dy = -1; dy <= 1; dy++) {
        int yy = y + dy;
        if (yy < 0 || yy >= HH) continue;
        const float* row = alpha + yy * WW;
        float4 a = *(const float4*)(row + x0);
        float lft = (x0 > 0) ? row[x0 - 1] : NEG;
        float rgt = (x0 + 4 < WW) ? row[x0 + 4] : NEG;
        h[0] = fmaxf(h[0], fmaxf(lft, fmaxf(a.x, a.y)));
        h[1] = fmaxf(h[1], fmaxf(a.x, fmaxf(a.y, a.z)));
        h[2] = fmaxf(h[2], fmaxf(a.y, fmaxf(a.z, a.w)));
        h[3] = fmaxf(h[3], fmaxf(a.z, fmaxf(a.w, rgt)));
    }
    float4 alive;
    alive.x = (h[0] > 0.1f) ? 1.0f : 0.0f;
    alive.y = (h[1] > 0.1f) ? 1.0f : 0.0f;
    alive.z = (h[2] > 0.1f) ? 1.0f : 0.0f;
    alive.w = (h[3] > 0.1f) ? 1.0f : 0.0f;
#pragma unroll
    for (int c = 0; c < CC; c++) {
        int idx = ((b * CC + c) * HH + y) * WW + x0;
        float4 v = *(const float4*)(nw + idx);
        v.x *= alive.x; v.y *= alive.y; v.z *= alive.z; v.w *= alive.w;
        *(float4*)(dst + idx) = v;
    }
}

// ---------------------------------------------------------------------------
extern "C" void kernel_launch(void* const* d_in, const int* in_sizes, int n_in,
                              void* d_out, int out_size)
{
    (void)in_sizes; (void)n_in; (void)out_size;
    const float* x  = (const float*)d_in[0];
    const float* w1 = (const float*)d_in[1];
    const float* b1 = (const float*)d_in[2];
    const float* w2 = (const float*)d_in[3];
    const float* b2 = (const float*)d_in[4];
    float* out = (float*)d_out;

    float* pState = nullptr;
    float* pNew = nullptr;
    unsigned char* pMask = nullptr;
    cudaGetSymbolAddress((void**)&pState, g_state);
    cudaGetSymbolAddress((void**)&pNew,   g_new);
    cudaGetSymbolAddress((void**)&pMask,  g_mask);

    cudaFuncSetAttribute(k_stepA, cudaFuncAttributeMaxDynamicSharedMemorySize, SMEM_TOT);

    k_keys<<<1, NSTEPS>>>();
    k_mask<<<(NSTEPS * NPIX) / 256, 256>>>();
    k_wsplit<<<(HID * KCH + CC * HID + 127) / 128, 128>>>(w1, w2);

    for (int s = 0; s < NSTEPS; s++) {
        const float* src = (s == 0) ? x : pState;
        k_stepA<<<GRID_A, 128, SMEM_TOT>>>(src, pNew, b1, b2, pMask + s * NPIX);
        float* dst = (s == NSTEPS - 1) ? out : pState;
        k_stepB<<<NPIX / 1024, 256>>>(pNew, dst);
    }
}

// round 11
// speedup vs baseline: 2.7344x; 1.5842x over previous
#include <cuda_runtime.h>
#include <cuda_bf16.h>
#include <cstdint>

// ---------------------------------------------------------------------------
// Neural CA, 16 steps. B=8, C=16, H=W=128, HID=128.
// GEMM1 + GEMM2 on mma.sync bf16 hi/lo split. Perception computed directly
// in A-fragment layout (no smem transpose, no syncs in the tile loop).
// ---------------------------------------------------------------------------

#define BB 8
#define CC 16
#define HH 128
#define WW 128
#define HID 128
#define NSTEPS 16
#define NPIX (BB*HH*WW)
#define SELEM (BB*CC*HH*WW)
#define KCH 48
#define NTILES (BB*HH)
#define GRID_A 592               /* 148 SMs x 4 blocks */

#define B_STRIDE 136     /* bf16: 272B = 17x16B, ldsm conflict-free */
#define W2_STRIDE 24     /* bf16: 48B = 3x16B, ldsm conflict-free */

__device__ float g_state[SELEM];
__device__ float g_new[SELEM];
__device__ unsigned char g_mask[NSTEPS*NPIX];
__device__ unsigned int g_keys[NSTEPS*2];
__device__ __nv_bfloat16 g_w1Thi[KCH*B_STRIDE];    // [c=48][o=128] padded
__device__ __nv_bfloat16 g_w1Tlo[KCH*B_STRIDE];
__device__ __nv_bfloat16 g_w2Thi[HID*W2_STRIDE];   // [k=128][n=16] padded
__device__ __nv_bfloat16 g_w2Tlo[HID*W2_STRIDE];

// ---------------------------------------------------------------------------
__device__ __forceinline__ uint32_t smem_u32(const void* p) {
    uint32_t a;
    asm("{ .reg .u64 t; cvta.to.shared.u64 t, %1; cvt.u32.u64 %0, t; }" : "=r"(a) : "l"(p));
    return a;
}
__device__ __forceinline__ void ldsm4t(uint32_t* r, uint32_t addr) {
    asm volatile("ldmatrix.sync.aligned.m8n8.x4.trans.shared.b16 {%0,%1,%2,%3}, [%4];"
        : "=r"(r[0]), "=r"(r[1]), "=r"(r[2]), "=r"(r[3]) : "r"(addr));
}
__device__ __forceinline__ void mma16816(float* c, const uint32_t* a, const uint32_t* b) {
    asm volatile("mma.sync.aligned.m16n8k16.row.col.f32.bf16.bf16.f32 "
        "{%0,%1,%2,%3}, {%4,%5,%6,%7}, {%8,%9}, {%0,%1,%2,%3};"
        : "+f"(c[0]), "+f"(c[1]), "+f"(c[2]), "+f"(c[3])
        : "r"(a[0]), "r"(a[1]), "r"(a[2]), "r"(a[3]), "r"(b[0]), "r"(b[1]));
}
__device__ __forceinline__ uint32_t pack_bf16x2(float a, float b) {
    __nv_bfloat162 v;
    v.x = __float2bfloat16(a);
    v.y = __float2bfloat16(b);
    return *(uint32_t*)&v;
}
// pack hi parts and compute lo residual pack
__device__ __forceinline__ void split_pack(float a, float b, uint32_t& hi, uint32_t& lo) {
    __nv_bfloat16 ha = __float2bfloat16(a);
    __nv_bfloat16 hb = __float2bfloat16(b);
    __nv_bfloat162 hv; hv.x = ha; hv.y = hb;
    hi = *(uint32_t*)&hv;
    lo = pack_bf16x2(a - __bfloat162float(ha), b - __bfloat162float(hb));
}

// ---------------------------------------------------------------------------
// threefry2x32 (exact JAX round structure, partitionable path)
// ---------------------------------------------------------------------------
__device__ __forceinline__ unsigned int rotl32(unsigned int v, int d) {
    return (v << d) | (v >> (32 - d));
}
__device__ __forceinline__ void threefry2x32(unsigned int k0, unsigned int k1,
                                             unsigned int x0, unsigned int x1,
                                             unsigned int& o0, unsigned int& o1) {
    unsigned int ks2 = k0 ^ k1 ^ 0x1BD11BDAu;
    x0 += k0; x1 += k1;
#define TF_G(r0,r1,r2,r3) \
    x0 += x1; x1 = rotl32(x1, r0); x1 ^= x0; \
    x0 += x1; x1 = rotl32(x1, r1); x1 ^= x0; \
    x0 += x1; x1 = rotl32(x1, r2); x1 ^= x0; \
    x0 += x1; x1 = rotl32(x1, r3); x1 ^= x0;
    TF_G(13,15,26,6);  x0 += k1;  x1 += ks2 + 1u;
    TF_G(17,29,16,24); x0 += ks2; x1 += k0  + 2u;
    TF_G(13,15,26,6);  x0 += k0;  x1 += k1  + 3u;
    TF_G(17,29,16,24); x0 += k1;  x1 += ks2 + 4u;
    TF_G(13,15,26,6);  x0 += ks2; x1 += k0  + 5u;
#undef TF_G
    o0 = x0; o1 = x1;
}

__global__ void k_keys() {
    int s = threadIdx.x;
    if (s < NSTEPS) {
        unsigned int o0, o1;
        threefry2x32(0u, 42u, 0u, (unsigned int)s, o0, o1);
        g_keys[2*s] = o0; g_keys[2*s+1] = o1;
    }
}

__global__ void k_mask() {
    int idx = blockIdx.x * blockDim.x + threadIdx.x;
    int s = idx >> 17;
    unsigned int i = (unsigned int)(idx & (NPIX - 1));
    unsigned int o0, o1;
    threefry2x32(g_keys[2*s], g_keys[2*s+1], 0u, i, o0, o1);
    unsigned int bits = o0 ^ o1;
    float u = __uint_as_float((bits >> 9) | 0x3f800000u) - 1.0f;
    g_mask[idx] = (u < 0.5f) ? 1 : 0;
}

// Pre-split w1 (transposed [c][o]) and w2 (transposed [k][n]) to bf16 hi/lo.
__global__ void k_wsplit(const float* __restrict__ w1, const float* __restrict__ w2) {
    int i = blockIdx.x * blockDim.x + threadIdx.x;
    if (i < HID * KCH) {                       // w1[o=128][c=48]
        int o = i / KCH, c = i % KCH;
        float v = w1[i];
        __nv_bfloat16 hi = __float2bfloat16(v);
        g_w1Thi[c * B_STRIDE + o] = hi;
        g_w1Tlo[c * B_STRIDE + o] = __float2bfloat16(v - __bfloat162float(hi));
    } else if (i < HID * KCH + CC * HID) {     // w2[n=16][k=128]
        int j = i - HID * KCH;
        int n = j >> 7, k = j & 127;
        float v = w2[n * HID + k];
        __nv_bfloat16 hi = __float2bfloat16(v);
        g_w2Thi[k * W2_STRIDE + n] = hi;
        g_w2Tlo[k * W2_STRIDE + n] = __float2bfloat16(v - __bfloat162float(hi));
    }
}

// ---------------------------------------------------------------------------
// Step A. Grid-stride over 1024 row-tiles; block = 128 thr (4 warps),
// warp handles 32 pixels (M=32, two m16 fragments), no smem A, no syncs.
// ---------------------------------------------------------------------------
#define OFF_BH  0                        /* 48*136*2 = 13056 */
#define OFF_BL  13056
#define OFF_W2H 26112                    /* 128*24*2 = 6144 */
#define OFF_W2L 32256
#define OFF_B1  38400                    /* 512 */
#define OFF_B2  38912                    /* 64 */
#define SMEM_TOT 38976

__global__ __launch_bounds__(128, 4)
void k_stepA(const float* __restrict__ src, float* __restrict__ dst,
             const float* __restrict__ b1, const float* __restrict__ b2,
             const unsigned char* __restrict__ msk)
{
    extern __shared__ char smem[];
    uint32_t sb = smem_u32(smem);

    int tid = threadIdx.x;
    int l   = tid & 31;
    int wid = tid >> 5;
    int wbase = wid * 32;
    int gid = l >> 2, tig = l & 3;

    // --- stage weights once per block ---
    {
        const uint4* s1h = (const uint4*)g_w1Thi;
        const uint4* s1l = (const uint4*)g_w1Tlo;
        uint4* d1h = (uint4*)(smem + OFF_BH);
        uint4* d1l = (uint4*)(smem + OFF_BL);
        for (int i = tid; i < (KCH * B_STRIDE * 2) / 16; i += 128) {
            d1h[i] = s1h[i]; d1l[i] = s1l[i];
        }
        const uint4* s2h = (const uint4*)g_w2Thi;
        const uint4* s2l = (const uint4*)g_w2Tlo;
        uint4* d2h = (uint4*)(smem + OFF_W2H);
        uint4* d2l = (uint4*)(smem + OFF_W2L);
        for (int i = tid; i < (HID * W2_STRIDE * 2) / 16; i += 128) {
            d2h[i] = s2h[i]; d2l[i] = s2l[i];
        }
        float* bs1 = (float*)(smem + OFF_B1);
        float* bs2 = (float*)(smem + OFF_B2);
        if (tid < HID) bs1[tid] = b1[tid];
        if (tid < CC)  bs2[tid] = b2[tid];
    }
    __syncthreads();

    const float* bs1 = (const float*)(smem + OFF_B1);
    const float* bs2 = (const float*)(smem + OFF_B2);

    for (int tile = blockIdx.x; tile < NTILES; tile += GRID_A) {
        int b = tile >> 7;
        int y = tile & 127;
        bool ym = (y > 0), yp = (y < HH - 1);

        // --- perception directly into A fragments ---
        // thread covers pixels x_j = wbase + gid + 8j (j=0..3),
        // channels {2tig, 2tig+1} (cp=0) and {2tig+8, 2tig+9} (cp=1).
        // frag index: m-frag = j>>1, reg = (j&1) + 2*cp. k: 0=ident,1=sx,2=sy.
        uint32_t ahi[2][3][4], alo[2][3][4];
#pragma unroll
        for (int cp = 0; cp < 2; cp++) {
            int c0 = 2 * tig + cp * 8;
            const float* pa = src + ((b * CC + c0) * HH) * WW;
            const float* pb = pa + HH * WW;
#pragma unroll
            for (int j = 0; j < 4; j++) {
                int x = wbase + gid + 8 * j;
                bool xm = (x > 0), xp = (x < WW - 1);
                float i0, sx0, sy0, i1, sx1, sy1;
#pragma unroll
                for (int cc = 0; cc < 2; cc++) {
                    const float* pc = cc ? pb : pa;
                    const float* r0 = pc + (y - 1) * WW;
                    const float* r1 = pc + y * WW;
                    const float* r2 = pc + (y + 1) * WW;
                    float v00 = (ym && xm) ? r0[x-1] : 0.0f;
                    float v01 =  ym        ? r0[x]   : 0.0f;
                    float v02 = (ym && xp) ? r0[x+1] : 0.0f;
                    float v10 =  xm        ? r1[x-1] : 0.0f;
                    float v11 =              r1[x];
                    float v12 =  xp        ? r1[x+1] : 0.0f;
                    float v20 = (yp && xm) ? r2[x-1] : 0.0f;
                    float v21 =  yp        ? r2[x]   : 0.0f;
                    float v22 = (yp && xp) ? r2[x+1] : 0.0f;
                    float sx = (v00 - v02 + 2.0f * (v10 - v12) + v20 - v22) * 0.125f;
                    float sy = (v00 + 2.0f * v01 + v02 - v20 - 2.0f * v21 - v22) * 0.125f;
                    if (cc == 0) { i0 = v11; sx0 = sx; sy0 = sy; }
                    else         { i1 = v11; sx1 = sx; sy1 = sy; }
                }
                int mf = j >> 1, rg = (j & 1) + 2 * cp;
                split_pack(i0,  i1,  ahi[mf][0][rg], alo[mf][0][rg]);
                split_pack(sx0, sx1, ahi[mf][1][rg], alo[mf][1][rg]);
                split_pack(sy0, sy1, ahi[mf][2][rg], alo[mf][2][rg]);
            }
        }

        // diff accumulators (GEMM2 C-frags), init with b2
        float d2f[2][2][4];
#pragma unroll
        for (int m = 0; m < 2; m++)
#pragma unroll
            for (int n = 0; n < 2; n++) {
                float q0 = bs2[n * 8 + tig * 2];
                float q1 = bs2[n * 8 + tig * 2 + 1];
                d2f[m][n][0] = q0; d2f[m][n][1] = q1;
                d2f[m][n][2] = q0; d2f[m][n][3] = q1;
            }

        uint32_t bro = (uint32_t)(l & 15) * (B_STRIDE * 2) + (uint32_t)(l >> 4) * 16;

#pragma unroll
        for (int pass = 0; pass < 4; pass++) {
            float acc[4][2][4];
#pragma unroll
            for (int nt = 0; nt < 4; nt++)
#pragma unroll
                for (int m = 0; m < 2; m++)
#pragma unroll
                    for (int q = 0; q < 4; q++) acc[nt][m][q] = 0.0f;

            // GEMM1 (N=32 this pass): acc += Ahi*Bhi + Ahi*Blo + Alo*Bhi
#pragma unroll
            for (int nt16 = 0; nt16 < 2; nt16++) {
                uint32_t ncol = (uint32_t)(pass * 32 + nt16 * 16) * 2;
#pragma unroll
                for (int k = 0; k < 3; k++) {
                    uint32_t off = (uint32_t)k * 16 * (B_STRIDE * 2) + bro + ncol;
                    uint32_t bh[4], bl[4];
                    ldsm4t(bh, sb + OFF_BH + off);
                    ldsm4t(bl, sb + OFF_BL + off);
#pragma unroll
                    for (int m = 0; m < 2; m++) {
                        mma16816(acc[nt16*2+0][m], ahi[m][k], bh + 0);
                        mma16816(acc[nt16*2+1][m], ahi[m][k], bh + 2);
                        mma16816(acc[nt16*2+0][m], ahi[m][k], bl + 0);
                        mma16816(acc[nt16*2+1][m], ahi[m][k], bl + 2);
                        mma16816(acc[nt16*2+0][m], alo[m][k], bh + 0);
                        mma16816(acc[nt16*2+1][m], alo[m][k], bh + 2);
                    }
                }
            }

            // GEMM2 partial: h = relu(acc+b1), split in regs, feed as A-frags
#pragma unroll
            for (int kk = 0; kk < 2; kk++) {
                uint32_t woff = ((uint32_t)(pass * 32 + kk * 16 + (l & 15)) * W2_STRIDE
                                 + (uint32_t)(l >> 4) * 8) * 2;
                uint32_t wh[4], wl[4];
                ldsm4t(wh, sb + OFF_W2H + woff);
                ldsm4t(wl, sb + OFF_W2L + woff);
                float b00 = bs1[pass*32 + kk*16 + tig*2];
                float b01 = bs1[pass*32 + kk*16 + tig*2 + 1];
                float b10 = bs1[pass*32 + kk*16 + 8 + tig*2];
                float b11 = bs1[pass*32 + kk*16 + 8 + tig*2 + 1];
#pragma unroll
                for (int m = 0; m < 2; m++) {
                    const float* c0 = acc[2*kk][m];
                    const float* c1 = acc[2*kk+1][m];
                    float h0 = fmaxf(c0[0] + b00, 0.0f), h1 = fmaxf(c0[1] + b01, 0.0f);
                    float h2 = fmaxf(c0[2] + b00, 0.0f), h3 = fmaxf(c0[3] + b01, 0.0f);
                    float h4 = fmaxf(c1[0] + b10, 0.0f), h5 = fmaxf(c1[1] + b11, 0.0f);
                    float h6 = fmaxf(c1[2] + b10, 0.0f), h7 = fmaxf(c1[3] + b11, 0.0f);
                    uint32_t ah2[4], al2[4];
                    split_pack(h0, h1, ah2[0], al2[0]);
                    split_pack(h2, h3, ah2[1], al2[1]);
                    split_pack(h4, h5, ah2[2], al2[2]);
                    split_pack(h6, h7, ah2[3], al2[3]);
                    mma16816(d2f[m][0], ah2, wh + 0);
                    mma16816(d2f[m][1], ah2, wh + 2);
                    mma16816(d2f[m][0], ah2, wl + 0);
                    mma16816(d2f[m][1], ah2, wl + 2);
                    mma16816(d2f[m][0], al2, wh + 0);
                    mma16816(d2f[m][1], al2, wh + 2);
                }
            }
        }

        // --- masked update straight from fragments (reload src, L1-hot) ---
        const unsigned char* mrow = msk + (b * HH + y) * WW;
#pragma unroll
        for (int j = 0; j < 4; j++) {
            int x = wbase + gid + 8 * j;
            int mf = j >> 1;
            float mj = mrow[x] ? 1.0f : 0.0f;
#pragma unroll
            for (int cp = 0; cp < 2; cp++) {
                int c0 = 2 * tig + cp * 8;
                const float* d = d2f[mf][cp];
                int i0 = ((b * CC + c0) * HH + y) * WW + x;
                int i1 = i0 + HH * WW;
                int rb = (j & 1) * 2;
                dst[i0] = src[i0] + d[rb]     * mj;
                dst[i1] = src[i1] + d[rb + 1] * mj;
            }
        }
    }
}

// ---------------------------------------------------------------------------
// Step B: 3x3 max-pool of alpha, alive gate. 4 pixels/thread via float4.
// ---------------------------------------------------------------------------
__global__ __launch_bounds__(256) void k_stepB(const float* __restrict__ nw,
                                               float* __restrict__ dst)
{
    int g = blockIdx.x * 256 + threadIdx.x;
    int p4 = g * 4;
    int b = p4 >> 14;
    int rem = p4 & 16383;
    int y = rem >> 7;
    int x0 = rem & 127;

    const float* alpha = nw + ((b * CC + 3) * HH) * WW;
    const float NEG = -3.402823466e38f;
    float h[4]; h[0] = h[1] = h[2] = h[3] = NEG;
#pragma unroll
    for (int dy = -1; dy <= 1; dy++) {
        int yy = y + dy;
        if (yy < 0 || yy >= HH) continue;
        const float* row = alpha + yy * WW;
        float4 a = *(const float4*)(row + x0);
        float lft = (x0 > 0) ? row[x0 - 1] : NEG;
        float rgt = (x0 + 4 < WW) ? row[x0 + 4] : NEG;
        h[0] = fmaxf(h[0], fmaxf(lft, fmaxf(a.x, a.y)));
        h[1] = fmaxf(h[1], fmaxf(a.x, fmaxf(a.y, a.z)));
        h[2] = fmaxf(h[2], fmaxf(a.y, fmaxf(a.z, a.w)));
        h[3] = fmaxf(h[3], fmaxf(a.z, fmaxf(a.w, rgt)));
    }
    float4 alive;
    alive.x = (h[0] > 0.1f) ? 1.0f : 0.0f;
    alive.y = (h[1] > 0.1f) ? 1.0f : 0.0f;
    alive.z = (h[2] > 0.1f) ? 1.0f : 0.0f;
    alive.w = (h[3] > 0.1f) ? 1.0f : 0.0f;
#pragma unroll
    for (int c = 0; c < CC; c++) {
        int idx = ((b * CC + c) * HH + y) * WW + x0;
        float4 v = *(const float4*)(nw + idx);
        v.x *= alive.x; v.y *= alive.y; v.z *= alive.z; v.w *= alive.w;
        *(float4*)(dst + idx) = v;
    }
}

// ---------------------------------------------------------------------------
extern "C" void kernel_launch(void* const* d_in, const int* in_sizes, int n_in,
                              void* d_out, int out_size)
{
    (void)in_sizes; (void)n_in; (void)out_size;
    const float* x  = (const float*)d_in[0];
    const float* w1 = (const float*)d_in[1];
    const float* b1 = (const float*)d_in[2];
    const float* w2 = (const float*)d_in[3];
    const float* b2 = (const float*)d_in[4];
    float* out = (float*)d_out;

    float* pState = nullptr;
    float* pNew = nullptr;
    unsigned char* pMask = nullptr;
    cudaGetSymbolAddress((void**)&pState, g_state);
    cudaGetSymbolAddress((void**)&pNew,   g_new);
    cudaGetSymbolAddress((void**)&pMask,  g_mask);

    cudaFuncSetAttribute(k_stepA, cudaFuncAttributeMaxDynamicSharedMemorySize, SMEM_TOT);

    k_keys<<<1, NSTEPS>>>();
    k_mask<<<(NSTEPS * NPIX) / 256, 256>>>();
    k_wsplit<<<(HID * KCH + CC * HID + 127) / 128, 128>>>(w1, w2);

    for (int s = 0; s < NSTEPS; s++) {
        const float* src = (s == 0) ? x : pState;
        k_stepA<<<GRID_A, 128, SMEM_TOT>>>(src, pNew, b1, b2, pMask + s * NPIX);
        float* dst = (s == NSTEPS - 1) ? out : pState;
        k_stepB<<<NPIX / 1024, 256>>>(pNew, dst);
    }
}

// round 14
// speedup vs baseline: 3.3404x; 1.2216x over previous
#include <cuda_runtime.h>
#include <cuda_bf16.h>
#include <cstdint>

// ---------------------------------------------------------------------------
// Neural CA, 16 steps. B=8, C=16, H=W=128, HID=128.
// GEMM1 + GEMM2 on mma.sync bf16 hi/lo split. Perception via cooperative
// smem staging of separable sobel partials (v, u=[1,2,1]_y, d=[1,0,-1]_y).
// ---------------------------------------------------------------------------

#define BB 8
#define CC 16
#define HH 128
#define WW 128
#define HID 128
#define NSTEPS 16
#define NPIX (BB*HH*WW)
#define SELEM (BB*CC*HH*WW)
#define KCH 48
#define NTILES (BB*HH)
#define GRID_A 444               /* 148 SMs x 3 blocks */

#define B_STRIDE 136     /* bf16: 272B = 17x16B, ldsm conflict-free */
#define W2_STRIDE 24     /* bf16: 48B = 3x16B, ldsm conflict-free */
#define S_STRIDE 140     /* fp32 words per channel plane row; banks 24*tig+gid */
#define PLANE (CC*S_STRIDE)      /* 2240 words */

__device__ float g_state[SELEM];
__device__ float g_new[SELEM];
__device__ unsigned char g_mask[NSTEPS*NPIX];
__device__ unsigned int g_keys[NSTEPS*2];
__device__ __nv_bfloat16 g_w1Thi[KCH*B_STRIDE];    // [c=48][o=128] padded
__device__ __nv_bfloat16 g_w1Tlo[KCH*B_STRIDE];
__device__ __nv_bfloat16 g_w2Thi[HID*W2_STRIDE];   // [k=128][n=16] padded
__device__ __nv_bfloat16 g_w2Tlo[HID*W2_STRIDE];

// ---------------------------------------------------------------------------
__device__ __forceinline__ uint32_t smem_u32(const void* p) {
    uint32_t a;
    asm("{ .reg .u64 t; cvta.to.shared.u64 t, %1; cvt.u32.u64 %0, t; }" : "=r"(a) : "l"(p));
    return a;
}
__device__ __forceinline__ void ldsm4t(uint32_t* r, uint32_t addr) {
    asm volatile("ldmatrix.sync.aligned.m8n8.x4.trans.shared.b16 {%0,%1,%2,%3}, [%4];"
        : "=r"(r[0]), "=r"(r[1]), "=r"(r[2]), "=r"(r[3]) : "r"(addr));
}
__device__ __forceinline__ void mma16816(float* c, const uint32_t* a, const uint32_t* b) {
    asm volatile("mma.sync.aligned.m16n8k16.row.col.f32.bf16.bf16.f32 "
        "{%0,%1,%2,%3}, {%4,%5,%6,%7}, {%8,%9}, {%0,%1,%2,%3};"
        : "+f"(c[0]), "+f"(c[1]), "+f"(c[2]), "+f"(c[3])
        : "r"(a[0]), "r"(a[1]), "r"(a[2]), "r"(a[3]), "r"(b[0]), "r"(b[1]));
}
__device__ __forceinline__ uint32_t pack_bf16x2(float a, float b) {
    __nv_bfloat162 v;
    v.x = __float2bfloat16(a);
    v.y = __float2bfloat16(b);
    return *(uint32_t*)&v;
}
__device__ __forceinline__ void split_pack(float a, float b, uint32_t& hi, uint32_t& lo) {
    __nv_bfloat16 ha = __float2bfloat16(a);
    __nv_bfloat16 hb = __float2bfloat16(b);
    __nv_bfloat162 hv; hv.x = ha; hv.y = hb;
    hi = *(uint32_t*)&hv;
    lo = pack_bf16x2(a - __bfloat162float(ha), b - __bfloat162float(hb));
}

// ---------------------------------------------------------------------------
// threefry2x32 (exact JAX round structure, partitionable path)
// ---------------------------------------------------------------------------
__device__ __forceinline__ unsigned int rotl32(unsigned int v, int d) {
    return (v << d) | (v >> (32 - d));
}
__device__ __forceinline__ void threefry2x32(unsigned int k0, unsigned int k1,
                                             unsigned int x0, unsigned int x1,
                                             unsigned int& o0, unsigned int& o1) {
    unsigned int ks2 = k0 ^ k1 ^ 0x1BD11BDAu;
    x0 += k0; x1 += k1;
#define TF_G(r0,r1,r2,r3) \
    x0 += x1; x1 = rotl32(x1, r0); x1 ^= x0; \
    x0 += x1; x1 = rotl32(x1, r1); x1 ^= x0; \
    x0 += x1; x1 = rotl32(x1, r2); x1 ^= x0; \
    x0 += x1; x1 = rotl32(x1, r3); x1 ^= x0;
    TF_G(13,15,26,6);  x0 += k1;  x1 += ks2 + 1u;
    TF_G(17,29,16,24); x0 += ks2; x1 += k0  + 2u;
    TF_G(13,15,26,6);  x0 += k0;  x1 += k1  + 3u;
    TF_G(17,29,16,24); x0 += k1;  x1 += ks2 + 4u;
    TF_G(13,15,26,6);  x0 += ks2; x1 += k0  + 5u;
#undef TF_G
    o0 = x0; o1 = x1;
}

__global__ void k_keys() {
    int s = threadIdx.x;
    if (s < NSTEPS) {
        unsigned int o0, o1;
        threefry2x32(0u, 42u, 0u, (unsigned int)s, o0, o1);
        g_keys[2*s] = o0; g_keys[2*s+1] = o1;
    }
}

__global__ void k_mask() {
    int idx = blockIdx.x * blockDim.x + threadIdx.x;
    int s = idx >> 17;
    unsigned int i = (unsigned int)(idx & (NPIX - 1));
    unsigned int o0, o1;
    threefry2x32(g_keys[2*s], g_keys[2*s+1], 0u, i, o0, o1);
    unsigned int bits = o0 ^ o1;
    float u = __uint_as_float((bits >> 9) | 0x3f800000u) - 1.0f;
    g_mask[idx] = (u < 0.5f) ? 1 : 0;
}

// Pre-split w1 (transposed [c][o]) and w2 (transposed [k][n]) to bf16 hi/lo.
__global__ void k_wsplit(const float* __restrict__ w1, const float* __restrict__ w2) {
    int i = blockIdx.x * blockDim.x + threadIdx.x;
    if (i < HID * KCH) {                       // w1[o=128][c=48]
        int o = i / KCH, c = i % KCH;
        float v = w1[i];
        __nv_bfloat16 hi = __float2bfloat16(v);
        g_w1Thi[c * B_STRIDE + o] = hi;
        g_w1Tlo[c * B_STRIDE + o] = __float2bfloat16(v - __bfloat162float(hi));
    } else if (i < HID * KCH + CC * HID) {     // w2[n=16][k=128]
        int j = i - HID * KCH;
        int n = j >> 7, k = j & 127;
        float v = w2[n * HID + k];
        __nv_bfloat16 hi = __float2bfloat16(v);
        g_w2Thi[k * W2_STRIDE + n] = hi;
        g_w2Tlo[k * W2_STRIDE + n] = __float2bfloat16(v - __bfloat162float(hi));
    }
}

// ---------------------------------------------------------------------------
// smem layout (bytes)
// ---------------------------------------------------------------------------
#define OFF_STAGE 0                       /* 3 planes * 2240 words * 4B = 26880 */
#define OFF_BH   26880                    /* 13056 */
#define OFF_BL   39936
#define OFF_W2H  52992                    /* 6144 */
#define OFF_W2L  59136
#define OFF_B1   65280                    /* 512 */
#define OFF_B2   65792                    /* 64 */
#define SMEM_TOT 65856

__global__ __launch_bounds__(128, 3)
void k_stepA(const float* __restrict__ src, float* __restrict__ dst,
             const float* __restrict__ b1, const float* __restrict__ b2,
             const unsigned char* __restrict__ msk)
{
    extern __shared__ char smem[];
    uint32_t sb = smem_u32(smem);
    float* sv = (float*)smem;            // v plane  [c][140], data at +4
    float* su = sv + PLANE;              // u plane
    float* sd = su + PLANE;              // d plane

    int tid = threadIdx.x;
    int l   = tid & 31;
    int wid = tid >> 5;
    int wbase = wid * 32;
    int gid = l >> 2, tig = l & 3;

    // --- stage weights + zero stencil halo words (once per block) ---
    {
        const uint4* s1h = (const uint4*)g_w1Thi;
        const uint4* s1l = (const uint4*)g_w1Tlo;
        uint4* d1h = (uint4*)(smem + OFF_BH);
        uint4* d1l = (uint4*)(smem + OFF_BL);
        for (int i = tid; i < (KCH * B_STRIDE * 2) / 16; i += 128) {
            d1h[i] = s1h[i]; d1l[i] = s1l[i];
        }
        const uint4* s2h = (const uint4*)g_w2Thi;
        const uint4* s2l = (const uint4*)g_w2Tlo;
        uint4* d2h = (uint4*)(smem + OFF_W2H);
        uint4* d2l = (uint4*)(smem + OFF_W2L);
        for (int i = tid; i < (HID * W2_STRIDE * 2) / 16; i += 128) {
            d2h[i] = s2h[i]; d2l[i] = s2l[i];
        }
        float* bs1 = (float*)(smem + OFF_B1);
        float* bs2 = (float*)(smem + OFF_B2);
        if (tid < HID) bs1[tid] = b1[tid];
        if (tid < CC)  bs2[tid] = b2[tid];
        // halo words (x=-1 at word 3, x=128 at word 132) in u and d planes: always 0
        if (tid < 64) {
            int pl = tid >> 5;            // 0:u, 1:d
            int c  = (tid >> 1) & 15;
            int e  = tid & 1;
            (pl ? sd : su)[c * S_STRIDE + (e ? 132 : 3)] = 0.0f;
        }
    }
    __syncthreads();

    const float* bs1 = (const float*)(smem + OFF_B1);
    const float* bs2 = (const float*)(smem + OFF_B2);
    uint32_t bro = (uint32_t)(l & 15) * (B_STRIDE * 2) + (uint32_t)(l >> 4) * 16;

    for (int tile = blockIdx.x; tile < NTILES; tile += GRID_A) {
        int b = tile >> 7;
        int y = tile & 127;
        bool ym = (y > 0), yp = (y < HH - 1);

        // --- cooperative staging: v, u = v0+2v1+v2, d = v0-v2 (float4) ---
#pragma unroll
        for (int kq = 0; kq < 4; kq++) {
            int idx = tid + 128 * kq;
            int c  = idx >> 5;
            int x0 = (idx & 31) << 2;
            const float* base = src + ((b * CC + c) * HH + y) * WW + x0;
            float4 r1 = *(const float4*)base;
            float4 r0 = ym ? *(const float4*)(base - WW) : make_float4(0.f, 0.f, 0.f, 0.f);
            float4 r2 = yp ? *(const float4*)(base + WW) : make_float4(0.f, 0.f, 0.f, 0.f);
            float4 u4, d4;
            u4.x = r0.x + 2.0f * r1.x + r2.x;  d4.x = r0.x - r2.x;
            u4.y = r0.y + 2.0f * r1.y + r2.y;  d4.y = r0.y - r2.y;
            u4.z = r0.z + 2.0f * r1.z + r2.z;  d4.z = r0.z - r2.z;
            u4.w = r0.w + 2.0f * r1.w + r2.w;  d4.w = r0.w - r2.w;
            int o = c * S_STRIDE + 4 + x0;
            *(float4*)(sv + o) = r1;
            *(float4*)(su + o) = u4;
            *(float4*)(sd + o) = d4;
        }
        __syncthreads();

        // --- stencil from smem directly into A fragments ---
        // thread: pixels x_j = wbase + gid + 8j, channels {2tig,2tig+1}+8cp
        float identr[2][4][2];
        uint32_t ahi[2][3][4], alo[2][3][4];
#pragma unroll
        for (int cp = 0; cp < 2; cp++) {
#pragma unroll
            for (int j = 0; j < 4; j++) {
                int x = wbase + gid + 8 * j;
                float iv[2], sxv[2], syv[2];
#pragma unroll
                for (int cc = 0; cc < 2; cc++) {
                    int c = 2 * tig + 8 * cp + cc;
                    const float* pv = sv + c * S_STRIDE + 4;
                    const float* pu = su + c * S_STRIDE + 4;
                    const float* pd = sd + c * S_STRIDE + 4;
                    iv[cc]  = pv[x];
                    sxv[cc] = (pu[x - 1] - pu[x + 1]) * 0.125f;
                    syv[cc] = (pd[x - 1] + 2.0f * pd[x] + pd[x + 1]) * 0.125f;
                }
                identr[cp][j][0] = iv[0];
                identr[cp][j][1] = iv[1];
                int mf = j >> 1, rg = (j & 1) + 2 * cp;
                split_pack(iv[0],  iv[1],  ahi[mf][0][rg], alo[mf][0][rg]);
                split_pack(sxv[0], sxv[1], ahi[mf][1][rg], alo[mf][1][rg]);
                split_pack(syv[0], syv[1], ahi[mf][2][rg], alo[mf][2][rg]);
            }
        }
        __syncthreads();   // all stage reads done; next staging may overwrite

        // diff accumulators (GEMM2 C-frags), init with b2
        float d2f[2][2][4];
#pragma unroll
        for (int m = 0; m < 2; m++)
#pragma unroll
            for (int n = 0; n < 2; n++) {
                float q0 = bs2[n * 8 + tig * 2];
                float q1 = bs2[n * 8 + tig * 2 + 1];
                d2f[m][n][0] = q0; d2f[m][n][1] = q1;
                d2f[m][n][2] = q0; d2f[m][n][3] = q1;
            }

#pragma unroll
        for (int pass = 0; pass < 4; pass++) {
            float acc[4][2][4];
#pragma unroll
            for (int nt = 0; nt < 4; nt++)
#pragma unroll
                for (int m = 0; m < 2; m++)
#pragma unroll
                    for (int q = 0; q < 4; q++) acc[nt][m][q] = 0.0f;

            // GEMM1 (N=32 this pass): acc += Ahi*Bhi + Ahi*Blo + Alo*Bhi
#pragma unroll
            for (int nt16 = 0; nt16 < 2; nt16++) {
                uint32_t ncol = (uint32_t)(pass * 32 + nt16 * 16) * 2;
#pragma unroll
                for (int k = 0; k < 3; k++) {
                    uint32_t off = (uint32_t)k * 16 * (B_STRIDE * 2) + bro + ncol;
                    uint32_t bh[4], bl[4];
                    ldsm4t(bh, sb + OFF_BH + off);
                    ldsm4t(bl, sb + OFF_BL + off);
#pragma unroll
                    for (int m = 0; m < 2; m++) {
                        mma16816(acc[nt16*2+0][m], ahi[m][k], bh + 0);
                        mma16816(acc[nt16*2+1][m], ahi[m][k], bh + 2);
                        mma16816(acc[nt16*2+0][m], ahi[m][k], bl + 0);
                        mma16816(acc[nt16*2+1][m], ahi[m][k], bl + 2);
                        mma16816(acc[nt16*2+0][m], alo[m][k], bh + 0);
                        mma16816(acc[nt16*2+1][m], alo[m][k], bh + 2);
                    }
                }
            }

            // GEMM2 partial: h = relu(acc+b1), split in regs, feed as A-frags
#pragma unroll
            for (int kk = 0; kk < 2; kk++) {
                uint32_t woff = ((uint32_t)(pass * 32 + kk * 16 + (l & 15)) * W2_STRIDE
                                 + (uint32_t)(l >> 4) * 8) * 2;
                uint32_t wh[4], wl[4];
                ldsm4t(wh, sb + OFF_W2H + woff);
                ldsm4t(wl, sb + OFF_W2L + woff);
                float b00 = bs1[pass*32 + kk*16 + tig*2];
                float b01 = bs1[pass*32 + kk*16 + tig*2 + 1];
                float b10 = bs1[pass*32 + kk*16 + 8 + tig*2];
                float b11 = bs1[pass*32 + kk*16 + 8 + tig*2 + 1];
#pragma unroll
                for (int m = 0; m < 2; m++) {
                    const float* c0 = acc[2*kk][m];
                    const float* c1 = acc[2*kk+1][m];
                    float h0 = fmaxf(c0[0] + b00, 0.0f), h1 = fmaxf(c0[1] + b01, 0.0f);
                    float h2 = fmaxf(c0[2] + b00, 0.0f), h3 = fmaxf(c0[3] + b01, 0.0f);
                    float h4 = fmaxf(c1[0] + b10, 0.0f), h5 = fmaxf(c1[1] + b11, 0.0f);
                    float h6 = fmaxf(c1[2] + b10, 0.0f), h7 = fmaxf(c1[3] + b11, 0.0f);
                    uint32_t ah2[4], al2[4];
                    split_pack(h0, h1, ah2[0], al2[0]);
                    split_pack(h2, h3, ah2[1], al2[1]);
                    split_pack(h4, h5, ah2[2], al2[2]);
                    split_pack(h6, h7, ah2[3], al2[3]);
                    mma16816(d2f[m][0], ah2, wh + 0);
                    mma16816(d2f[m][1], ah2, wh + 2);
                    mma16816(d2f[m][0], ah2, wl + 0);
                    mma16816(d2f[m][1], ah2, wl + 2);
                    mma16816(d2f[m][0], al2, wh + 0);
                    mma16816(d2f[m][1], al2, wh + 2);
                }
            }
        }

        // --- masked update straight from fragments (ident from registers) ---
        const unsigned char* mrow = msk + (b * HH + y) * WW;
#pragma unroll
        for (int j = 0; j < 4; j++) {
            int x = wbase + gid + 8 * j;
            int mf = j >> 1;
            float mj = mrow[x] ? 1.0f : 0.0f;
#pragma unroll
            for (int cp = 0; cp < 2; cp++) {
                int c0 = 2 * tig + cp * 8;
                const float* d = d2f[mf][cp];
                int i0 = ((b * CC + c0) * HH + y) * WW + x;
                int i1 = i0 + HH * WW;
                int rb = (j & 1) * 2;
                dst[i0] = identr[cp][j][0] + d[rb]     * mj;
                dst[i1] = identr[cp][j][1] + d[rb + 1] * mj;
            }
        }
    }
}

// ---------------------------------------------------------------------------
// Step B: 3x3 max-pool of alpha, alive gate. 4 px/thread, 128 thr, 256 blocks.
// ---------------------------------------------------------------------------
__global__ __launch_bounds__(128) void k_stepB(const float* __restrict__ nw,
                                               float* __restrict__ dst)
{
    int g = blockIdx.x * 128 + threadIdx.x;
    int p4 = g * 4;
    int b = p4 >> 14;
    int rem = p4 & 16383;
    int y = rem >> 7;
    int x0 = rem & 127;

    const float* alpha = nw + ((b * CC + 3) * HH) * WW;
    const float NEG = -3.402823466e38f;
    float h[4]; h[0] = h[1] = h[2] = h[3] = NEG;
#pragma unroll
    for (int dy = -1; dy <= 1; dy++) {
        int yy = y + dy;
        if (yy < 0 || yy >= HH) continue;
        const float* row = alpha + yy * WW;
        float4 a = *(const float4*)(row + x0);
        float lft = (x0 > 0) ? row[x0 - 1] : NEG;
        float rgt = (x0 + 4 < WW) ? row[x0 + 4] : NEG;
        h[0] = fmaxf(h[0], fmaxf(lft, fmaxf(a.x, a.y)));
        h[1] = fmaxf(h[1], fmaxf(a.x, fmaxf(a.y, a.z)));
        h[2] = fmaxf(h[2], fmaxf(a.y, fmaxf(a.z, a.w)));
        h[3] = fmaxf(h[3], fmaxf(a.z, fmaxf(a.w, rgt)));
    }
    float4 alive;
    alive.x = (h[0] > 0.1f) ? 1.0f : 0.0f;
    alive.y = (h[1] > 0.1f) ? 1.0f : 0.0f;
    alive.z = (h[2] > 0.1f) ? 1.0f : 0.0f;
    alive.w = (h[3] > 0.1f) ? 1.0f : 0.0f;
#pragma unroll
    for (int c = 0; c < CC; c++) {
        int idx = ((b * CC + c) * HH + y) * WW + x0;
        float4 v = *(const float4*)(nw + idx);
        v.x *= alive.x; v.y *= alive.y; v.z *= alive.z; v.w *= alive.w;
        *(float4*)(dst + idx) = v;
    }
}

// ---------------------------------------------------------------------------
extern "C" void kernel_launch(void* const* d_in, const int* in_sizes, int n_in,
                              void* d_out, int out_size)
{
    (void)in_sizes; (void)n_in; (void)out_size;
    const float* x  = (const float*)d_in[0];
    const float* w1 = (const float*)d_in[1];
    const float* b1 = (const float*)d_in[2];
    const float* w2 = (const float*)d_in[3];
    const float* b2 = (const float*)d_in[4];
    float* out = (float*)d_out;

    float* pState = nullptr;
    float* pNew = nullptr;
    unsigned char* pMask = nullptr;
    cudaGetSymbolAddress((void**)&pState, g_state);
    cudaGetSymbolAddress((void**)&pNew,   g_new);
    cudaGetSymbolAddress((void**)&pMask,  g_mask);

    cudaFuncSetAttribute(k_stepA, cudaFuncAttributeMaxDynamicSharedMemorySize, SMEM_TOT);

    k_keys<<<1, NSTEPS>>>();
    k_mask<<<(NSTEPS * NPIX) / 256, 256>>>();
    k_wsplit<<<(HID * KCH + CC * HID + 127) / 128, 128>>>(w1, w2);

    for (int s = 0; s < NSTEPS; s++) {
        const float* src = (s == 0) ? x : pState;
        k_stepA<<<GRID_A, 128, SMEM_TOT>>>(src, pNew, b1, b2, pMask + s * NPIX);
        float* dst = (s == NSTEPS - 1) ? out : pState;
        k_stepB<<<NPIX / 512, 128>>>(pNew, dst);
    }
}

// round 15
// speedup vs baseline: 3.4646x; 1.0372x over previous
#include <cuda_runtime.h>
#include <cuda_bf16.h>
#include <cstdint>

// ---------------------------------------------------------------------------
// Neural CA, 16 steps. B=8, C=16, H=W=128, HID=128.
// GEMM1 + GEMM2 on mma.sync bf16 hi/lo split. Weights as fragment-ordered
// global tables (L1-resident LDG.128, no smem, no LDSM). Perception via
// smem staging of separable sobel partials.
// ---------------------------------------------------------------------------

#define BB 8
#define CC 16
#define HH 128
#define WW 128
#define HID 128
#define NSTEPS 16
#define NPIX (BB*HH*WW)
#define SELEM (BB*CC*HH*WW)
#define KCH 48
#define NTILES (BB*HH)
#define GRID_A 592               /* 148 SMs x 4 blocks */

#define B_STRIDE 136     /* bf16, for prep-kernel ldsm staging */
#define W2_STRIDE 24
#define S_STRIDE 140     /* fp32 words per channel plane row; banks 24*tig+gid */
#define PLANE (CC*S_STRIDE)      /* 2240 words */

__device__ float g_state[SELEM];
__device__ float g_new[SELEM];
__device__ unsigned char g_mask[NSTEPS*NPIX];
__device__ unsigned int g_keys[NSTEPS*2];
__device__ __nv_bfloat16 g_w1Thi[KCH*B_STRIDE];    // [c=48][o=128] padded
__device__ __nv_bfloat16 g_w1Tlo[KCH*B_STRIDE];
__device__ __nv_bfloat16 g_w2Thi[HID*W2_STRIDE];   // [k=128][n=16] padded
__device__ __nv_bfloat16 g_w2Tlo[HID*W2_STRIDE];
// fragment tables: [frag pair (hi,lo) interleaved][lane] of uint4
__device__ uint4 g_fragW1[4*2*3*2*32];   // (pass,nt16,k)x(h,l) -> 24.6 KB
__device__ uint4 g_fragW2[4*2*2*32];     // (pass,kk)x(h,l)     -> 8 KB

// ---------------------------------------------------------------------------
__device__ __forceinline__ uint32_t smem_u32(const void* p) {
    uint32_t a;
    asm("{ .reg .u64 t; cvta.to.shared.u64 t, %1; cvt.u32.u64 %0, t; }" : "=r"(a) : "l"(p));
    return a;
}
__device__ __forceinline__ void ldsm4t(uint32_t* r, uint32_t addr) {
    asm volatile("ldmatrix.sync.aligned.m8n8.x4.trans.shared.b16 {%0,%1,%2,%3}, [%4];"
        : "=r"(r[0]), "=r"(r[1]), "=r"(r[2]), "=r"(r[3]) : "r"(addr));
}
__device__ __forceinline__ void mma16816(float* c, const uint32_t* a, const uint32_t* b) {
    asm volatile("mma.sync.aligned.m16n8k16.row.col.f32.bf16.bf16.f32 "
        "{%0,%1,%2,%3}, {%4,%5,%6,%7}, {%8,%9}, {%0,%1,%2,%3};"
        : "+f"(c[0]), "+f"(c[1]), "+f"(c[2]), "+f"(c[3])
        : "r"(a[0]), "r"(a[1]), "r"(a[2]), "r"(a[3]), "r"(b[0]), "r"(b[1]));
}
__device__ __forceinline__ uint32_t pack_bf16x2(float a, float b) {
    __nv_bfloat162 v;
    v.x = __float2bfloat16(a);
    v.y = __float2bfloat16(b);
    return *(uint32_t*)&v;
}
__device__ __forceinline__ void split_pack(float a, float b, uint32_t& hi, uint32_t& lo) {
    __nv_bfloat16 ha = __float2bfloat16(a);
    __nv_bfloat16 hb = __float2bfloat16(b);
    __nv_bfloat162 hv; hv.x = ha; hv.y = hb;
    hi = *(uint32_t*)&hv;
    lo = pack_bf16x2(a - __bfloat162float(ha), b - __bfloat162float(hb));
}

// ---------------------------------------------------------------------------
// threefry2x32 (exact JAX round structure, partitionable path)
// ---------------------------------------------------------------------------
__device__ __forceinline__ unsigned int rotl32(unsigned int v, int d) {
    return (v << d) | (v >> (32 - d));
}
__device__ __forceinline__ void threefry2x32(unsigned int k0, unsigned int k1,
                                             unsigned int x0, unsigned int x1,
                                             unsigned int& o0, unsigned int& o1) {
    unsigned int ks2 = k0 ^ k1 ^ 0x1BD11BDAu;
    x0 += k0; x1 += k1;
#define TF_G(r0,r1,r2,r3) \
    x0 += x1; x1 = rotl32(x1, r0); x1 ^= x0; \
    x0 += x1; x1 = rotl32(x1, r1); x1 ^= x0; \
    x0 += x1; x1 = rotl32(x1, r2); x1 ^= x0; \
    x0 += x1; x1 = rotl32(x1, r3); x1 ^= x0;
    TF_G(13,15,26,6);  x0 += k1;  x1 += ks2 + 1u;
    TF_G(17,29,16,24); x0 += ks2; x1 += k0  + 2u;
    TF_G(13,15,26,6);  x0 += k0;  x1 += k1  + 3u;
    TF_G(17,29,16,24); x0 += k1;  x1 += ks2 + 4u;
    TF_G(13,15,26,6);  x0 += ks2; x1 += k0  + 5u;
#undef TF_G
    o0 = x0; o1 = x1;
}

__global__ void k_keys() {
    int s = threadIdx.x;
    if (s < NSTEPS) {
        unsigned int o0, o1;
        threefry2x32(0u, 42u, 0u, (unsigned int)s, o0, o1);
        g_keys[2*s] = o0; g_keys[2*s+1] = o1;
    }
}

__global__ void k_mask() {
    int idx = blockIdx.x * blockDim.x + threadIdx.x;
    int s = idx >> 17;
    unsigned int i = (unsigned int)(idx & (NPIX - 1));
    unsigned int o0, o1;
    threefry2x32(g_keys[2*s], g_keys[2*s+1], 0u, i, o0, o1);
    unsigned int bits = o0 ^ o1;
    float u = __uint_as_float((bits >> 9) | 0x3f800000u) - 1.0f;
    g_mask[idx] = (u < 0.5f) ? 1 : 0;
}

// Pre-split w1 (transposed [c][o]) and w2 (transposed [k][n]) to bf16 hi/lo.
__global__ void k_wsplit(const float* __restrict__ w1, const float* __restrict__ w2) {
    int i = blockIdx.x * blockDim.x + threadIdx.x;
    if (i < HID * KCH) {                       // w1[o=128][c=48]
        int o = i / KCH, c = i % KCH;
        float v = w1[i];
        __nv_bfloat16 hi = __float2bfloat16(v);
        g_w1Thi[c * B_STRIDE + o] = hi;
        g_w1Tlo[c * B_STRIDE + o] = __float2bfloat16(v - __bfloat162float(hi));
    } else if (i < HID * KCH + CC * HID) {     // w2[n=16][k=128]
        int j = i - HID * KCH;
        int n = j >> 7, k = j & 127;
        float v = w2[n * HID + k];
        __nv_bfloat16 hi = __float2bfloat16(v);
        g_w2Thi[k * W2_STRIDE + n] = hi;
        g_w2Tlo[k * W2_STRIDE + n] = __float2bfloat16(v - __bfloat162float(hi));
    }
}

// ---------------------------------------------------------------------------
// Prep: build fragment-ordered weight tables by running the SAME ldsm4t calls
// the hot loop used previously, then storing the registers to global.
// 1 block, 32 threads.
// ---------------------------------------------------------------------------
#define WF_BH  0
#define WF_BL  13056
#define WF_W2H 26112
#define WF_W2L 32256
#define WF_TOT 38400

__global__ void k_wfrag() {
    extern __shared__ char smem[];
    uint32_t sb = smem_u32(smem);
    int l = threadIdx.x;

    {
        const uint4* s1h = (const uint4*)g_w1Thi;
        const uint4* s1l = (const uint4*)g_w1Tlo;
        uint4* d1h = (uint4*)(smem + WF_BH);
        uint4* d1l = (uint4*)(smem + WF_BL);
        for (int i = l; i < (KCH * B_STRIDE * 2) / 16; i += 32) {
            d1h[i] = s1h[i]; d1l[i] = s1l[i];
        }
        const uint4* s2h = (const uint4*)g_w2Thi;
        const uint4* s2l = (const uint4*)g_w2Tlo;
        uint4* d2h = (uint4*)(smem + WF_W2H);
        uint4* d2l = (uint4*)(smem + WF_W2L);
        for (int i = l; i < (HID * W2_STRIDE * 2) / 16; i += 32) {
            d2h[i] = s2h[i]; d2l[i] = s2l[i];
        }
    }
    __syncwarp();

    uint32_t bro = (uint32_t)(l & 15) * (B_STRIDE * 2) + (uint32_t)(l >> 4) * 16;
    for (int pass = 0; pass < 4; pass++)
        for (int nt16 = 0; nt16 < 2; nt16++)
            for (int k = 0; k < 3; k++) {
                uint32_t off = (uint32_t)k * 16 * (B_STRIDE * 2) + bro
                             + (uint32_t)(pass * 32 + nt16 * 16) * 2;
                uint32_t bh[4], bl[4];
                ldsm4t(bh, sb + WF_BH + off);
                ldsm4t(bl, sb + WF_BL + off);
                int fidx = ((pass * 2 + nt16) * 3 + k) * 2;
                g_fragW1[(fidx + 0) * 32 + l] = *(uint4*)bh;
                g_fragW1[(fidx + 1) * 32 + l] = *(uint4*)bl;
            }

    for (int pass = 0; pass < 4; pass++)
        for (int kk = 0; kk < 2; kk++) {
            uint32_t woff = ((uint32_t)(pass * 32 + kk * 16 + (l & 15)) * W2_STRIDE
                             + (uint32_t)(l >> 4) * 8) * 2;
            uint32_t wh[4], wl[4];
            ldsm4t(wh, sb + WF_W2H + woff);
            ldsm4t(wl, sb + WF_W2L + woff);
            int fidx = (pass * 2 + kk) * 2;
            g_fragW2[(fidx + 0) * 32 + l] = *(uint4*)wh;
            g_fragW2[(fidx + 1) * 32 + l] = *(uint4*)wl;
        }
}

// ---------------------------------------------------------------------------
// Step A. smem = stage planes + biases only (27.5 KB) -> 4 blocks/SM.
// ---------------------------------------------------------------------------
#define OFF_B1   (3*PLANE*4)              /* 26880 */
#define OFF_B2   (OFF_B1 + 512)
#define SMEM_TOT (OFF_B2 + 64)

__global__ __launch_bounds__(128, 4)
void k_stepA(const float* __restrict__ src, float* __restrict__ dst,
             const float* __restrict__ b1, const float* __restrict__ b2,
             const unsigned char* __restrict__ msk)
{
    extern __shared__ char smem[];
    float* sv = (float*)smem;            // v plane  [c][140], data at +4
    float* su = sv + PLANE;              // u plane
    float* sd = su + PLANE;              // d plane

    int tid = threadIdx.x;
    int l   = tid & 31;
    int wid = tid >> 5;
    int wbase = wid * 32;
    int gid = l >> 2, tig = l & 3;

    // --- biases + halo zeros (once per block) ---
    {
        float* bs1 = (float*)(smem + OFF_B1);
        float* bs2 = (float*)(smem + OFF_B2);
        if (tid < HID) bs1[tid] = b1[tid];
        if (tid < CC)  bs2[tid] = b2[tid];
        if (tid < 64) {
            int pl = tid >> 5;            // 0:u, 1:d
            int c  = (tid >> 1) & 15;
            int e  = tid & 1;
            (pl ? sd : su)[c * S_STRIDE + (e ? 132 : 3)] = 0.0f;
        }
    }
    __syncthreads();

    const float* bs1 = (const float*)(smem + OFF_B1);
    const float* bs2 = (const float*)(smem + OFF_B2);
    const uint4* fw1 = g_fragW1 + l;
    const uint4* fw2 = g_fragW2 + l;

    for (int tile = blockIdx.x; tile < NTILES; tile += GRID_A) {
        int b = tile >> 7;
        int y = tile & 127;
        bool ym = (y > 0), yp = (y < HH - 1);

        // --- cooperative staging: v, u = v0+2v1+v2, d = v0-v2 (float4) ---
#pragma unroll
        for (int kq = 0; kq < 4; kq++) {
            int idx = tid + 128 * kq;
            int c  = idx >> 5;
            int x0 = (idx & 31) << 2;
            const float* base = src + ((b * CC + c) * HH + y) * WW + x0;
            float4 r1 = *(const float4*)base;
            float4 r0 = ym ? *(const float4*)(base - WW) : make_float4(0.f, 0.f, 0.f, 0.f);
            float4 r2 = yp ? *(const float4*)(base + WW) : make_float4(0.f, 0.f, 0.f, 0.f);
            float4 u4, d4;
            u4.x = r0.x + 2.0f * r1.x + r2.x;  d4.x = r0.x - r2.x;
            u4.y = r0.y + 2.0f * r1.y + r2.y;  d4.y = r0.y - r2.y;
            u4.z = r0.z + 2.0f * r1.z + r2.z;  d4.z = r0.z - r2.z;
            u4.w = r0.w + 2.0f * r1.w + r2.w;  d4.w = r0.w - r2.w;
            int o = c * S_STRIDE + 4 + x0;
            *(float4*)(sv + o) = r1;
            *(float4*)(su + o) = u4;
            *(float4*)(sd + o) = d4;
        }
        __syncthreads();

        // --- stencil from smem directly into A fragments ---
        uint32_t ahi[2][3][4], alo[2][3][4];
#pragma unroll
        for (int cp = 0; cp < 2; cp++) {
#pragma unroll
            for (int j = 0; j < 4; j++) {
                int x = wbase + gid + 8 * j;
                float iv[2], sxv[2], syv[2];
#pragma unroll
                for (int cc = 0; cc < 2; cc++) {
                    int c = 2 * tig + 8 * cp + cc;
                    const float* pv = sv + c * S_STRIDE + 4;
                    const float* pu = su + c * S_STRIDE + 4;
                    const float* pd = sd + c * S_STRIDE + 4;
                    iv[cc]  = pv[x];
                    sxv[cc] = (pu[x - 1] - pu[x + 1]) * 0.125f;
                    syv[cc] = (pd[x - 1] + 2.0f * pd[x] + pd[x + 1]) * 0.125f;
                }
                int mf = j >> 1, rg = (j & 1) + 2 * cp;
                split_pack(iv[0],  iv[1],  ahi[mf][0][rg], alo[mf][0][rg]);
                split_pack(sxv[0], sxv[1], ahi[mf][1][rg], alo[mf][1][rg]);
                split_pack(syv[0], syv[1], ahi[mf][2][rg], alo[mf][2][rg]);
            }
        }

        // diff accumulators (GEMM2 C-frags), init with b2
        float d2f[2][2][4];
#pragma unroll
        for (int m = 0; m < 2; m++)
#pragma unroll
            for (int n = 0; n < 2; n++) {
                float q0 = bs2[n * 8 + tig * 2];
                float q1 = bs2[n * 8 + tig * 2 + 1];
                d2f[m][n][0] = q0; d2f[m][n][1] = q1;
                d2f[m][n][2] = q0; d2f[m][n][3] = q1;
            }

#pragma unroll
        for (int pass = 0; pass < 4; pass++) {
            float acc[4][2][4];
#pragma unroll
            for (int nt = 0; nt < 4; nt++)
#pragma unroll
                for (int m = 0; m < 2; m++)
#pragma unroll
                    for (int q = 0; q < 4; q++) acc[nt][m][q] = 0.0f;

            // GEMM1 (N=32 this pass): acc += Ahi*Bhi + Ahi*Blo + Alo*Bhi
#pragma unroll
            for (int nt16 = 0; nt16 < 2; nt16++) {
#pragma unroll
                for (int k = 0; k < 3; k++) {
                    int fidx = ((pass * 2 + nt16) * 3 + k) * 2;
                    uint4 vh = fw1[fidx * 32];
                    uint4 vl = fw1[(fidx + 1) * 32];
                    uint32_t bh[4] = {vh.x, vh.y, vh.z, vh.w};
                    uint32_t bl[4] = {vl.x, vl.y, vl.z, vl.w};
#pragma unroll
                    for (int m = 0; m < 2; m++) {
                        mma16816(acc[nt16*2+0][m], ahi[m][k], bh + 0);
                        mma16816(acc[nt16*2+1][m], ahi[m][k], bh + 2);
                        mma16816(acc[nt16*2+0][m], ahi[m][k], bl + 0);
                        mma16816(acc[nt16*2+1][m], ahi[m][k], bl + 2);
                        mma16816(acc[nt16*2+0][m], alo[m][k], bh + 0);
                        mma16816(acc[nt16*2+1][m], alo[m][k], bh + 2);
                    }
                }
            }

            // GEMM2 partial: h = relu(acc+b1), split in regs, feed as A-frags
#pragma unroll
            for (int kk = 0; kk < 2; kk++) {
                int fidx = (pass * 2 + kk) * 2;
                uint4 vh = fw2[fidx * 32];
                uint4 vl = fw2[(fidx + 1) * 32];
                uint32_t wh[4] = {vh.x, vh.y, vh.z, vh.w};
                uint32_t wl[4] = {vl.x, vl.y, vl.z, vl.w};
                float b00 = bs1[pass*32 + kk*16 + tig*2];
                float b01 = bs1[pass*32 + kk*16 + tig*2 + 1];
                float b10 = bs1[pass*32 + kk*16 + 8 + tig*2];
                float b11 = bs1[pass*32 + kk*16 + 8 + tig*2 + 1];
#pragma unroll
                for (int m = 0; m < 2; m++) {
                    const float* c0 = acc[2*kk][m];
                    const float* c1 = acc[2*kk+1][m];
                    float h0 = fmaxf(c0[0] + b00, 0.0f), h1 = fmaxf(c0[1] + b01, 0.0f);
                    float h2 = fmaxf(c0[2] + b00, 0.0f), h3 = fmaxf(c0[3] + b01, 0.0f);
                    float h4 = fmaxf(c1[0] + b10, 0.0f), h5 = fmaxf(c1[1] + b11, 0.0f);
                    float h6 = fmaxf(c1[2] + b10, 0.0f), h7 = fmaxf(c1[3] + b11, 0.0f);
                    uint32_t ah2[4], al2[4];
                    split_pack(h0, h1, ah2[0], al2[0]);
                    split_pack(h2, h3, ah2[1], al2[1]);
                    split_pack(h4, h5, ah2[2], al2[2]);
                    split_pack(h6, h7, ah2[3], al2[3]);
                    mma16816(d2f[m][0], ah2, wh + 0);
                    mma16816(d2f[m][1], ah2, wh + 2);
                    mma16816(d2f[m][0], ah2, wl + 0);
                    mma16816(d2f[m][1], ah2, wl + 2);
                    mma16816(d2f[m][0], al2, wh + 0);
                    mma16816(d2f[m][1], al2, wh + 2);
                }
            }
        }

        // --- masked update; ident re-read from sv plane (LDS, conflict-free) ---
        const unsigned char* mrow = msk + (b * HH + y) * WW;
#pragma unroll
        for (int j = 0; j < 4; j++) {
            int x = wbase + gid + 8 * j;
            int mf = j >> 1;
            float mj = mrow[x] ? 1.0f : 0.0f;
#pragma unroll
            for (int cp = 0; cp < 2; cp++) {
                int c0 = 2 * tig + cp * 8;
                const float* d = d2f[mf][cp];
                int i0 = ((b * CC + c0) * HH + y) * WW + x;
                int i1 = i0 + HH * WW;
                int rb = (j & 1) * 2;
                dst[i0] = sv[c0 * S_STRIDE + 4 + x]       + d[rb]     * mj;
                dst[i1] = sv[(c0 + 1) * S_STRIDE + 4 + x] + d[rb + 1] * mj;
            }
        }
        __syncthreads();    // sv reads done before next tile's staging
    }
}

// ---------------------------------------------------------------------------
// Step B: 3x3 max-pool of alpha, alive gate. 4 px/thread, 128 thr, 256 blocks.
// ---------------------------------------------------------------------------
__global__ __launch_bounds__(128) void k_stepB(const float* __restrict__ nw,
                                               float* __restrict__ dst)
{
    int g = blockIdx.x * 128 + threadIdx.x;
    int p4 = g * 4;
    int b = p4 >> 14;
    int rem = p4 & 16383;
    int y = rem >> 7;
    int x0 = rem & 127;

    const float* alpha = nw + ((b * CC + 3) * HH) * WW;
    const float NEG = -3.402823466e38f;
    float h[4]; h[0] = h[1] = h[2] = h[3] = NEG;
#pragma unroll
    for (int dy = -1; dy <= 1; dy++) {
        int yy = y + dy;
        if (yy < 0 || yy >= HH) continue;
        const float* row = alpha + yy * WW;
        float4 a = *(const float4*)(row + x0);
        float lft = (x0 > 0) ? row[x0 - 1] : NEG;
        float rgt = (x0 + 4 < WW) ? row[x0 + 4] : NEG;
        h[0] = fmaxf(h[0], fmaxf(lft, fmaxf(a.x, a.y)));
        h[1] = fmaxf(h[1], fmaxf(a.x, fmaxf(a.y, a.z)));
        h[2] = fmaxf(h[2], fmaxf(a.y, fmaxf(a.z, a.w)));
        h[3] = fmaxf(h[3], fmaxf(a.z, fmaxf(a.w, rgt)));
    }
    float4 alive;
    alive.x = (h[0] > 0.1f) ? 1.0f : 0.0f;
    alive.y = (h[1] > 0.1f) ? 1.0f : 0.0f;
    alive.z = (h[2] > 0.1f) ? 1.0f : 0.0f;
    alive.w = (h[3] > 0.1f) ? 1.0f : 0.0f;
#pragma unroll
    for (int c = 0; c < CC; c++) {
        int idx = ((b * CC + c) * HH + y) * WW + x0;
        float4 v = *(const float4*)(nw + idx);
        v.x *= alive.x; v.y *= alive.y; v.z *= alive.z; v.w *= alive.w;
        *(float4*)(dst + idx) = v;
    }
}

// ---------------------------------------------------------------------------
extern "C" void kernel_launch(void* const* d_in, const int* in_sizes, int n_in,
                              void* d_out, int out_size)
{
    (void)in_sizes; (void)n_in; (void)out_size;
    const float* x  = (const float*)d_in[0];
    const float* w1 = (const float*)d_in[1];
    const float* b1 = (const float*)d_in[2];
    const float* w2 = (const float*)d_in[3];
    const float* b2 = (const float*)d_in[4];
    float* out = (float*)d_out;

    float* pState = nullptr;
    float* pNew = nullptr;
    unsigned char* pMask = nullptr;
    cudaGetSymbolAddress((void**)&pState, g_state);
    cudaGetSymbolAddress((void**)&pNew,   g_new);
    cudaGetSymbolAddress((void**)&pMask,  g_mask);

    cudaFuncSetAttribute(k_stepA, cudaFuncAttributeMaxDynamicSharedMemorySize, SMEM_TOT);
    cudaFuncSetAttribute(k_wfrag, cudaFuncAttributeMaxDynamicSharedMemorySize, WF_TOT);

    k_keys<<<1, NSTEPS>>>();
    k_mask<<<(NSTEPS * NPIX) / 256, 256>>>();
    k_wsplit<<<(HID * KCH + CC * HID + 127) / 128, 128>>>(w1, w2);
    k_wfrag<<<1, 32, WF_TOT>>>();

    for (int s = 0; s < NSTEPS; s++) {
        const float* src = (s == 0) ? x : pState;
        k_stepA<<<GRID_A, 128, SMEM_TOT>>>(src, pNew, b1, b2, pMask + s * NPIX);
        float* dst = (s == NSTEPS - 1) ? out : pState;
        k_stepB<<<NPIX / 512, 128>>>(pNew, dst);
    }
}